// round 7
// baseline (speedup 1.0000x reference)
#include <cuda_runtime.h>
#include <cuda_bf16.h>
#include <stdint.h>

#define A_DIM 128
#define N_DIM 64
#define H_DIM 1024
#define NJOBS 2048

#define ZSTR 136   // bf16 elems per z row   (272B: 8 ldmatrix rows cover 32 banks)
#define FSTR 136   // filterbank row stride
#define TSTR2 72   // tT row stride (144B, same property)

// Filterbanks, bf16 hi/lo, padded natural layout [row][stride]
__device__ __align__(16) unsigned short g_FyH[64 * FSTR];
__device__ __align__(16) unsigned short g_FyL[64 * FSTR];
__device__ __align__(16) unsigned short g_FxH[64 * FSTR];
__device__ __align__(16) unsigned short g_FxL[64 * FSTR];

// ---------------- helpers ----------------
__device__ __forceinline__ uint32_t smem_u32(const void* p) {
    uint32_t a;
    asm("{ .reg .u64 t; cvta.to.shared.u64 t, %1; cvt.u32.u64 %0, t; }" : "=r"(a) : "l"(p));
    return a;
}
// pack two f32 -> bf16x2; first arg lands in bits[15:0]
__device__ __forceinline__ uint32_t pkbf(float lo, float hi) {
    uint32_t r;
    asm("cvt.rn.bf16x2.f32 %0, %1, %2;" : "=r"(r) : "f"(hi), "f"(lo));
    return r;
}
__device__ __forceinline__ void ldsm4(uint32_t a, uint32_t* r) {
    asm volatile("ldmatrix.sync.aligned.m8n8.x4.shared.b16 {%0,%1,%2,%3}, [%4];"
                 : "=r"(r[0]), "=r"(r[1]), "=r"(r[2]), "=r"(r[3]) : "r"(a));
}
__device__ __forceinline__ void ldsm4t(uint32_t a, uint32_t* r) {
    asm volatile("ldmatrix.sync.aligned.m8n8.x4.trans.shared.b16 {%0,%1,%2,%3}, [%4];"
                 : "=r"(r[0]), "=r"(r[1]), "=r"(r[2]), "=r"(r[3]) : "r"(a));
}
__device__ __forceinline__ void mma16816(float* c, const uint32_t* a, const uint32_t* b) {
    asm volatile(
        "mma.sync.aligned.m16n8k16.row.col.f32.bf16.bf16.f32 "
        "{%0,%1,%2,%3}, {%4,%5,%6,%7}, {%8,%9}, {%0,%1,%2,%3};"
        : "+f"(c[0]), "+f"(c[1]), "+f"(c[2]), "+f"(c[3])
        : "r"(a[0]), "r"(a[1]), "r"(a[2]), "r"(a[3]), "r"(b[0]), "r"(b[1]));
}

// ---------------- setup: params -> split filterbanks ----------------
__global__ void setup_kernel(const float* __restrict__ h,
                             const float* __restrict__ Ww,
                             const float* __restrict__ Wb) {
    __shared__ float red[256];
    __shared__ float s_params[5];
    __shared__ float s_scal[5];
    int tid = threadIdx.x;

    for (int i = 0; i < 5; i++) {
        float p = 0.f;
        for (int j = tid; j < H_DIM; j += 256) p += Ww[i * H_DIM + j] * h[j];
        red[tid] = p;
        __syncthreads();
        for (int s = 128; s > 0; s >>= 1) {
            if (tid < s) red[tid] += red[tid + s];
            __syncthreads();
        }
        if (tid == 0) s_params[i] = red[0] + Wb[i];
        __syncthreads();
    }

    if (tid == 0) {
        float gtX = s_params[0];
        float gtY = s_params[1];
        float var = expf(s_params[2] + 1e-8f);
        float dd  = expf(s_params[3]) * (float)(A_DIM - 1) / (float)(N_DIM - 1);
        float gamma = expf(s_params[4]);
        s_scal[0] = (float)(A_DIM + 1) * (gtX + 1.f) * 0.5f;
        s_scal[1] = (float)(A_DIM + 1) * (gtY + 1.f) * 0.5f;
        s_scal[2] = dd;
        s_scal[3] = 1.f / (2.f * var);
        s_scal[4] = gamma;
    }
    __syncthreads();
    float gX = s_scal[0], gY = s_scal[1], dd = s_scal[2];
    float i2v = s_scal[3], gamma = s_scal[4];

    float sx = 0.f, sy = 0.f;
    for (int idx = tid; idx < N_DIM * A_DIM; idx += 256) {
        int n = idx >> 7, a = idx & 127;
        float off = ((float)n - (float)N_DIM * 0.5f - 0.5f) * dd;
        float da = (float)a - (gX + off);
        float db = (float)a - (gY + off);
        sx += expf(-da * da * i2v);
        sy += expf(-db * db * i2v);
    }
    red[tid] = sx;
    __syncthreads();
    for (int s = 128; s > 0; s >>= 1) { if (tid < s) red[tid] += red[tid + s]; __syncthreads(); }
    float sumX = red[0];
    __syncthreads();
    red[tid] = sy;
    __syncthreads();
    for (int s = 128; s > 0; s >>= 1) { if (tid < s) red[tid] += red[tid + s]; __syncthreads(); }
    float sumY = red[0];
    __syncthreads();

    float invX = 1.f / sumX;
    float invYg = gamma / sumY;

    for (int idx = tid; idx < N_DIM * A_DIM; idx += 256) {
        int n = idx >> 7, a = idx & 127;
        float off = ((float)n - (float)N_DIM * 0.5f - 0.5f) * dd;
        float da = (float)a - (gX + off);
        float db = (float)a - (gY + off);
        float fy = expf(-db * db * i2v) * invYg;  // gamma folded
        float fx = expf(-da * da * i2v) * invX;

        unsigned short yh = __bfloat16_as_ushort(__float2bfloat16(fy));
        float yhf = __uint_as_float(((uint32_t)yh) << 16);
        unsigned short yl = __bfloat16_as_ushort(__float2bfloat16(fy - yhf));
        unsigned short xhb = __bfloat16_as_ushort(__float2bfloat16(fx));
        float xhf = __uint_as_float(((uint32_t)xhb) << 16);
        unsigned short xl = __bfloat16_as_ushort(__float2bfloat16(fx - xhf));

        g_FyH[n * FSTR + a] = yh;
        g_FyL[n * FSTR + a] = yl;
        g_FxH[n * FSTR + a] = xhb;
        g_FxL[n * FSTR + a] = xl;
    }
}

// ---------------- SMEM layout (bytes) ----------------
#define SM_ZH   0
#define SM_ZL   34816
#define SM_TH   69632
#define SM_TL   88064
#define SM_FYH  106496
#define SM_FYL  123904
#define SM_FXH  141312
#define SM_FXL  158720
#define SM_TOTAL 176128

__global__ __launch_bounds__(512, 1)
void filt_mma(const float* __restrict__ x, const float* __restrict__ xh,
              float* __restrict__ out, int gridn) {
    extern __shared__ char sm[];
    int tid = threadIdx.x;
    int wid = tid >> 5, lane = tid & 31;
    int grp = lane >> 3, li = lane & 7;
    int qt = lane >> 2;          // t/4 : fragment row group
    int qr = (lane & 3) * 2;     // 2*(t%4) : fragment col pair

    // stage split filterbanks once per CTA
    {
        const uint4* s;
        uint4* d;
        s = (const uint4*)g_FyH; d = (uint4*)(sm + SM_FYH);
        for (int i = tid; i < 1088; i += 512) d[i] = s[i];
        s = (const uint4*)g_FyL; d = (uint4*)(sm + SM_FYL);
        for (int i = tid; i < 1088; i += 512) d[i] = s[i];
        s = (const uint4*)g_FxH; d = (uint4*)(sm + SM_FXH);
        for (int i = tid; i < 1088; i += 512) d[i] = s[i];
        s = (const uint4*)g_FxL; d = (uint4*)(sm + SM_FXL);
        for (int i = tid; i < 1088; i += 512) d[i] = s[i];
    }

    uint32_t sb = smem_u32(sm);

    // lane-constant ldmatrix byte offsets
    int radd = (grp >> 1) * 8;   // +8 rows for matrices 2,3
    int cadd = (grp & 1) * 8;    // +8 cols for matrices 1,3

    // ---- stage 1 mapping: 16 warps = 8 b-groups x 2 n-halves ----
    int bg = wid & 7;            // b-group
    int nh = wid >> 3;           // n-half (0/1)
    int b0w = bg * 16;
    uint32_t offA1 = (uint32_t)(((li + radd) * ZSTR + b0w + cadd) * 2);
    uint32_t offB1[2];
#pragma unroll
    for (int q = 0; q < 2; q++)
        offB1[q] = (uint32_t)(((nh * 32 + 16 * q + li + radd) * FSTR + cadd) * 2);

    // ---- stage 2 mapping: 16 warps = 4 n-strips x 4 m-quarters ----
    int n0 = (wid >> 2) * 16;
    int m0 = (wid & 3) * 16;
    uint32_t offA2 = (uint32_t)(((li + radd) * TSTR2 + n0 + cadd) * 2);
    uint32_t offB2 = (uint32_t)(((m0 + li + radd) * FSTR + cadd) * 2);

    __syncthreads();

    for (int job = blockIdx.x; job < NJOBS; job += gridn) {
        int which = job >> 10;
        int img = job & 1023;
        const float* src = (which ? xh : x) + (size_t)img * (A_DIM * A_DIM);

        // ---- 1. z -> smem bf16 hi/lo, padded [a][b] ----
        {
            const float4* s4 = (const float4*)src;
#pragma unroll
            for (int i = 0; i < 8; i++) {
                int e4 = tid + (i << 9);
                float4 v = __ldg(s4 + e4);
                int e = e4 << 2;
                int a = e >> 7, b = e & 127;
                uint32_t hA = pkbf(v.x, v.y), hB = pkbf(v.z, v.w);
                float l0 = v.x - __uint_as_float(hA << 16);
                float l1 = v.y - __uint_as_float(hA & 0xFFFF0000u);
                float l2 = v.z - __uint_as_float(hB << 16);
                float l3 = v.w - __uint_as_float(hB & 0xFFFF0000u);
                uint32_t lA = pkbf(l0, l1), lB = pkbf(l2, l3);
                uint32_t boff = (uint32_t)((a * ZSTR + b) * 2);
                *(uint2*)(sm + SM_ZH + boff) = make_uint2(hA, hB);
                *(uint2*)(sm + SM_ZL + boff) = make_uint2(lA, lB);
            }
        }
        __syncthreads();

        // ---- 2. stage 1: tT[b][n] = sum_a z[a][b]*Fy[n][a] (3-term split) ----
        {
            float acc[4][4];
#pragma unroll
            for (int j = 0; j < 4; j++)
#pragma unroll
                for (int c = 0; c < 4; c++) acc[j][c] = 0.f;

#pragma unroll
            for (int s = 0; s < 8; s++) {
                uint32_t Ah[4], Al[4], Bh[8], Bl[8];
                uint32_t aoff = offA1 + (uint32_t)(s * 16 * ZSTR * 2);
                ldsm4t(sb + SM_ZH + aoff, Ah);
                ldsm4t(sb + SM_ZL + aoff, Al);
#pragma unroll
                for (int q = 0; q < 2; q++) {
                    uint32_t boff = offB1[q] + (uint32_t)(s * 32);
                    ldsm4(sb + SM_FYH + boff, Bh + 4 * q);
                    ldsm4(sb + SM_FYL + boff, Bl + 4 * q);
                }
#pragma unroll
                for (int j = 0; j < 4; j++) {
                    mma16816(acc[j], Ah, Bh + 2 * j);
                    mma16816(acc[j], Ah, Bl + 2 * j);
                    mma16816(acc[j], Al, Bh + 2 * j);
                }
            }

            // write tT hi/lo
            int r0 = b0w + qt, r1 = r0 + 8;
#pragma unroll
            for (int j = 0; j < 4; j++) {
                int nj = nh * 32 + 8 * j + qr;
                uint32_t h01 = pkbf(acc[j][0], acc[j][1]);
                float d0 = acc[j][0] - __uint_as_float(h01 << 16);
                float d1 = acc[j][1] - __uint_as_float(h01 & 0xFFFF0000u);
                uint32_t l01 = pkbf(d0, d1);
                uint32_t h23 = pkbf(acc[j][2], acc[j][3]);
                float d2 = acc[j][2] - __uint_as_float(h23 << 16);
                float d3 = acc[j][3] - __uint_as_float(h23 & 0xFFFF0000u);
                uint32_t l23 = pkbf(d2, d3);
                *(uint32_t*)(sm + SM_TH + (r0 * TSTR2 + nj) * 2) = h01;
                *(uint32_t*)(sm + SM_TL + (r0 * TSTR2 + nj) * 2) = l01;
                *(uint32_t*)(sm + SM_TH + (r1 * TSTR2 + nj) * 2) = h23;
                *(uint32_t*)(sm + SM_TL + (r1 * TSTR2 + nj) * 2) = l23;
            }
        }
        __syncthreads();

        // ---- 3. stage 2: C[n][m] = sum_b t[n][b]*Fx[m][b] (3-term split) ----
        {
            float acc[2][4];
#pragma unroll
            for (int j = 0; j < 2; j++)
#pragma unroll
                for (int c = 0; c < 4; c++) acc[j][c] = 0.f;

#pragma unroll
            for (int s = 0; s < 8; s++) {
                uint32_t Ah[4], Al[4], Bh[4], Bl[4];
                uint32_t aoff = offA2 + (uint32_t)(s * 16 * TSTR2 * 2);
                ldsm4t(sb + SM_TH + aoff, Ah);
                ldsm4t(sb + SM_TL + aoff, Al);
                uint32_t boff = offB2 + (uint32_t)(s * 32);
                ldsm4(sb + SM_FXH + boff, Bh);
                ldsm4(sb + SM_FXL + boff, Bl);
#pragma unroll
                for (int j = 0; j < 2; j++) {
                    mma16816(acc[j], Ah, Bh + 2 * j);
                    mma16816(acc[j], Ah, Bl + 2 * j);
                    mma16816(acc[j], Al, Bh + 2 * j);
                }
            }

            float* ob = out + (size_t)img * (2 * N_DIM * N_DIM) + which * (N_DIM * N_DIM);
            int nA = n0 + qt, nB = nA + 8;
#pragma unroll
            for (int j = 0; j < 2; j++) {
                int m = m0 + 8 * j + qr;
                *(float2*)(ob + nA * N_DIM + m) = make_float2(acc[j][0], acc[j][1]);
                *(float2*)(ob + nB * N_DIM + m) = make_float2(acc[j][2], acc[j][3]);
            }
        }
        __syncthreads();
    }
}

extern "C" void kernel_launch(void* const* d_in, const int* in_sizes, int n_in,
                              void* d_out, int out_size) {
    const float* x  = (const float*)d_in[0];
    const float* xh = (const float*)d_in[1];
    const float* h  = (const float*)d_in[2];
    const float* Ww = (const float*)d_in[3];
    const float* Wb = (const float*)d_in[4];
    float* out = (float*)d_out;

    int sms = 148;
    cudaDeviceGetAttribute(&sms, cudaDevAttrMultiProcessorCount, 0);
    if (sms <= 0) sms = 148;

    cudaFuncSetAttribute(filt_mma, cudaFuncAttributeMaxDynamicSharedMemorySize, SM_TOTAL);

    setup_kernel<<<1, 256>>>(h, Ww, Wb);
    filt_mma<<<sms, 512, SM_TOTAL>>>(x, xh, out, sms);
}

// round 8
// speedup vs baseline: 1.1136x; 1.1136x over previous
#include <cuda_runtime.h>
#include <cuda_bf16.h>
#include <stdint.h>

#define A_DIM 128
#define N_DIM 64
#define H_DIM 1024
#define NJOBS 2048

#define ZSTR 136   // bf16 elems per z row   (272B: 8 ldmatrix rows cover 32 banks)
#define FSTR 136   // filterbank row stride
#define TSTR2 72   // tT row stride (144B, same property)

// Filterbanks, bf16 hi/lo, padded natural layout [row][stride]
__device__ __align__(16) unsigned short g_FyH[64 * FSTR];
__device__ __align__(16) unsigned short g_FyL[64 * FSTR];
__device__ __align__(16) unsigned short g_FxH[64 * FSTR];
__device__ __align__(16) unsigned short g_FxL[64 * FSTR];

// ---------------- helpers ----------------
__device__ __forceinline__ uint32_t smem_u32(const void* p) {
    uint32_t a;
    asm("{ .reg .u64 t; cvta.to.shared.u64 t, %1; cvt.u32.u64 %0, t; }" : "=r"(a) : "l"(p));
    return a;
}
// pack two f32 -> bf16x2; first arg lands in bits[15:0]
__device__ __forceinline__ uint32_t pkbf(float lo, float hi) {
    uint32_t r;
    asm("cvt.rn.bf16x2.f32 %0, %1, %2;" : "=r"(r) : "f"(hi), "f"(lo));
    return r;
}
__device__ __forceinline__ void ldsm4(uint32_t a, uint32_t* r) {
    asm volatile("ldmatrix.sync.aligned.m8n8.x4.shared.b16 {%0,%1,%2,%3}, [%4];"
                 : "=r"(r[0]), "=r"(r[1]), "=r"(r[2]), "=r"(r[3]) : "r"(a));
}
__device__ __forceinline__ void ldsm4t(uint32_t a, uint32_t* r) {
    asm volatile("ldmatrix.sync.aligned.m8n8.x4.trans.shared.b16 {%0,%1,%2,%3}, [%4];"
                 : "=r"(r[0]), "=r"(r[1]), "=r"(r[2]), "=r"(r[3]) : "r"(a));
}
__device__ __forceinline__ void mma16816(float* c, const uint32_t* a, const uint32_t* b) {
    asm volatile(
        "mma.sync.aligned.m16n8k16.row.col.f32.bf16.bf16.f32 "
        "{%0,%1,%2,%3}, {%4,%5,%6,%7}, {%8,%9}, {%0,%1,%2,%3};"
        : "+f"(c[0]), "+f"(c[1]), "+f"(c[2]), "+f"(c[3])
        : "r"(a[0]), "r"(a[1]), "r"(a[2]), "r"(a[3]), "r"(b[0]), "r"(b[1]));
}

// ---------------- setup: params -> split filterbanks ----------------
__global__ void setup_kernel(const float* __restrict__ h,
                             const float* __restrict__ Ww,
                             const float* __restrict__ Wb) {
    __shared__ float red[256];
    __shared__ float s_params[5];
    __shared__ float s_scal[5];
    int tid = threadIdx.x;

    for (int i = 0; i < 5; i++) {
        float p = 0.f;
        for (int j = tid; j < H_DIM; j += 256) p += Ww[i * H_DIM + j] * h[j];
        red[tid] = p;
        __syncthreads();
        for (int s = 128; s > 0; s >>= 1) {
            if (tid < s) red[tid] += red[tid + s];
            __syncthreads();
        }
        if (tid == 0) s_params[i] = red[0] + Wb[i];
        __syncthreads();
    }

    if (tid == 0) {
        float gtX = s_params[0];
        float gtY = s_params[1];
        float var = expf(s_params[2] + 1e-8f);
        float dd  = expf(s_params[3]) * (float)(A_DIM - 1) / (float)(N_DIM - 1);
        float gamma = expf(s_params[4]);
        s_scal[0] = (float)(A_DIM + 1) * (gtX + 1.f) * 0.5f;
        s_scal[1] = (float)(A_DIM + 1) * (gtY + 1.f) * 0.5f;
        s_scal[2] = dd;
        s_scal[3] = 1.f / (2.f * var);
        s_scal[4] = gamma;
    }
    __syncthreads();
    float gX = s_scal[0], gY = s_scal[1], dd = s_scal[2];
    float i2v = s_scal[3], gamma = s_scal[4];

    float sx = 0.f, sy = 0.f;
    for (int idx = tid; idx < N_DIM * A_DIM; idx += 256) {
        int n = idx >> 7, a = idx & 127;
        float off = ((float)n - (float)N_DIM * 0.5f - 0.5f) * dd;
        float da = (float)a - (gX + off);
        float db = (float)a - (gY + off);
        sx += expf(-da * da * i2v);
        sy += expf(-db * db * i2v);
    }
    red[tid] = sx;
    __syncthreads();
    for (int s = 128; s > 0; s >>= 1) { if (tid < s) red[tid] += red[tid + s]; __syncthreads(); }
    float sumX = red[0];
    __syncthreads();
    red[tid] = sy;
    __syncthreads();
    for (int s = 128; s > 0; s >>= 1) { if (tid < s) red[tid] += red[tid + s]; __syncthreads(); }
    float sumY = red[0];
    __syncthreads();

    float invX = 1.f / sumX;
    float invYg = gamma / sumY;

    for (int idx = tid; idx < N_DIM * A_DIM; idx += 256) {
        int n = idx >> 7, a = idx & 127;
        float off = ((float)n - (float)N_DIM * 0.5f - 0.5f) * dd;
        float da = (float)a - (gX + off);
        float db = (float)a - (gY + off);
        float fy = expf(-db * db * i2v) * invYg;  // gamma folded
        float fx = expf(-da * da * i2v) * invX;

        unsigned short yh = __bfloat16_as_ushort(__float2bfloat16(fy));
        float yhf = __uint_as_float(((uint32_t)yh) << 16);
        unsigned short yl = __bfloat16_as_ushort(__float2bfloat16(fy - yhf));
        unsigned short xhb = __bfloat16_as_ushort(__float2bfloat16(fx));
        float xhf = __uint_as_float(((uint32_t)xhb) << 16);
        unsigned short xl = __bfloat16_as_ushort(__float2bfloat16(fx - xhf));

        g_FyH[n * FSTR + a] = yh;
        g_FyL[n * FSTR + a] = yl;
        g_FxH[n * FSTR + a] = xhb;
        g_FxL[n * FSTR + a] = xl;
    }
}

// ---------------- SMEM layout (bytes) ----------------
#define SM_ZH   0
#define SM_ZL   34816
#define SM_TH   69632
#define SM_TL   88064
#define SM_FYH  106496
#define SM_FYL  123904
#define SM_FXH  141312
#define SM_FXL  158720
#define SM_TOTAL 176128

__global__ __launch_bounds__(512, 1)
void filt_mma(const float* __restrict__ x, const float* __restrict__ xh,
              float* __restrict__ out, int gridn) {
    extern __shared__ char sm[];
    int tid = threadIdx.x;
    int wid = tid >> 5, lane = tid & 31;
    int grp = lane >> 3, li = lane & 7;
    int qt = lane >> 2;          // t/4 : fragment row group
    int qr = (lane & 3) * 2;     // 2*(t%4) : fragment col pair

    // stage split filterbanks once per CTA
    {
        const uint4* s;
        uint4* d;
        s = (const uint4*)g_FyH; d = (uint4*)(sm + SM_FYH);
        for (int i = tid; i < 1088; i += 512) d[i] = s[i];
        s = (const uint4*)g_FyL; d = (uint4*)(sm + SM_FYL);
        for (int i = tid; i < 1088; i += 512) d[i] = s[i];
        s = (const uint4*)g_FxH; d = (uint4*)(sm + SM_FXH);
        for (int i = tid; i < 1088; i += 512) d[i] = s[i];
        s = (const uint4*)g_FxL; d = (uint4*)(sm + SM_FXL);
        for (int i = tid; i < 1088; i += 512) d[i] = s[i];
    }

    uint32_t sb = smem_u32(sm);

    // lane-constant ldmatrix byte offsets
    int radd = (grp >> 1) * 8;   // +8 rows for matrices 2,3
    int cadd = (grp & 1) * 8;    // +8 cols for matrices 1,3

    // ---- stage 1 mapping: 16 warps = 8 b-groups x 2 n-halves ----
    int bg = wid & 7;            // b-group
    int nh = wid >> 3;           // n-half (0/1)
    int b0w = bg * 16;
    uint32_t offA1 = (uint32_t)(((li + radd) * ZSTR + b0w + cadd) * 2);
    uint32_t offB1[2];
#pragma unroll
    for (int q = 0; q < 2; q++)
        offB1[q] = (uint32_t)(((nh * 32 + 16 * q + li + radd) * FSTR + cadd) * 2);

    // ---- stage 2 mapping: 16 warps = 4 n-strips x 4 m-quarters ----
    int n0 = (wid >> 2) * 16;
    int m0 = (wid & 3) * 16;
    uint32_t offA2 = (uint32_t)(((li + radd) * TSTR2 + n0 + cadd) * 2);
    uint32_t offB2 = (uint32_t)(((m0 + li + radd) * FSTR + cadd) * 2);

    __syncthreads();

    // register prefetch of first job's z tile
    float4 pre[8];
    {
        int job0 = blockIdx.x;
        const float* src = ((job0 >> 10) ? xh : x) + (size_t)(job0 & 1023) * (A_DIM * A_DIM);
        const float4* s4 = (const float4*)src;
#pragma unroll
        for (int i = 0; i < 8; i++) pre[i] = __ldg(s4 + tid + (i << 9));
    }

    for (int job = blockIdx.x; job < NJOBS; job += gridn) {
        int which = job >> 10;
        int img = job & 1023;

        // ---- 1. convert prefetched z regs -> smem bf16 hi/lo panels ----
        {
#pragma unroll
            for (int i = 0; i < 8; i++) {
                int e4 = tid + (i << 9);
                float4 v = pre[i];
                int e = e4 << 2;
                int a = e >> 7, b = e & 127;
                uint32_t hA = pkbf(v.x, v.y), hB = pkbf(v.z, v.w);
                float l0 = v.x - __uint_as_float(hA << 16);
                float l1 = v.y - __uint_as_float(hA & 0xFFFF0000u);
                float l2 = v.z - __uint_as_float(hB << 16);
                float l3 = v.w - __uint_as_float(hB & 0xFFFF0000u);
                uint32_t lA = pkbf(l0, l1), lB = pkbf(l2, l3);
                uint32_t boff = (uint32_t)((a * ZSTR + b) * 2);
                *(uint2*)(sm + SM_ZH + boff) = make_uint2(hA, hB);
                *(uint2*)(sm + SM_ZL + boff) = make_uint2(lA, lB);
            }
        }
        __syncthreads();

        // ---- issue prefetch for next job (latency hidden behind both MMA stages) ----
        {
            int nj = job + gridn;
            if (nj < NJOBS) {
                const float* nsrc = ((nj >> 10) ? xh : x) + (size_t)(nj & 1023) * (A_DIM * A_DIM);
                const float4* ns4 = (const float4*)nsrc;
#pragma unroll
                for (int i = 0; i < 8; i++) pre[i] = __ldg(ns4 + tid + (i << 9));
            }
        }

        // ---- 2. stage 1: tT[b][n] = sum_a z[a][b]*Fy[n][a] (3-term split) ----
        {
            float acc[4][4];
#pragma unroll
            for (int j = 0; j < 4; j++)
#pragma unroll
                for (int c = 0; c < 4; c++) acc[j][c] = 0.f;

#pragma unroll
            for (int s = 0; s < 8; s++) {
                uint32_t Ah[4], Al[4], Bh[8], Bl[8];
                uint32_t aoff = offA1 + (uint32_t)(s * 16 * ZSTR * 2);
                ldsm4t(sb + SM_ZH + aoff, Ah);
                ldsm4t(sb + SM_ZL + aoff, Al);
#pragma unroll
                for (int q = 0; q < 2; q++) {
                    uint32_t boff = offB1[q] + (uint32_t)(s * 32);
                    ldsm4(sb + SM_FYH + boff, Bh + 4 * q);
                    ldsm4(sb + SM_FYL + boff, Bl + 4 * q);
                }
#pragma unroll
                for (int j = 0; j < 4; j++) {
                    mma16816(acc[j], Ah, Bh + 2 * j);
                    mma16816(acc[j], Ah, Bl + 2 * j);
                    mma16816(acc[j], Al, Bh + 2 * j);
                }
            }

            // write tT hi/lo
            int r0 = b0w + qt, r1 = r0 + 8;
#pragma unroll
            for (int j = 0; j < 4; j++) {
                int nj2 = nh * 32 + 8 * j + qr;
                uint32_t h01 = pkbf(acc[j][0], acc[j][1]);
                float d0 = acc[j][0] - __uint_as_float(h01 << 16);
                float d1 = acc[j][1] - __uint_as_float(h01 & 0xFFFF0000u);
                uint32_t l01 = pkbf(d0, d1);
                uint32_t h23 = pkbf(acc[j][2], acc[j][3]);
                float d2 = acc[j][2] - __uint_as_float(h23 << 16);
                float d3 = acc[j][3] - __uint_as_float(h23 & 0xFFFF0000u);
                uint32_t l23 = pkbf(d2, d3);
                *(uint32_t*)(sm + SM_TH + (r0 * TSTR2 + nj2) * 2) = h01;
                *(uint32_t*)(sm + SM_TL + (r0 * TSTR2 + nj2) * 2) = l01;
                *(uint32_t*)(sm + SM_TH + (r1 * TSTR2 + nj2) * 2) = h23;
                *(uint32_t*)(sm + SM_TL + (r1 * TSTR2 + nj2) * 2) = l23;
            }
        }
        __syncthreads();

        // ---- 3. stage 2: C[n][m] = sum_b t[n][b]*Fx[m][b] (3-term split) ----
        {
            float acc[2][4];
#pragma unroll
            for (int j = 0; j < 2; j++)
#pragma unroll
                for (int c = 0; c < 4; c++) acc[j][c] = 0.f;

#pragma unroll
            for (int s = 0; s < 8; s++) {
                uint32_t Ah[4], Al[4], Bh[4], Bl[4];
                uint32_t aoff = offA2 + (uint32_t)(s * 16 * TSTR2 * 2);
                ldsm4t(sb + SM_TH + aoff, Ah);
                ldsm4t(sb + SM_TL + aoff, Al);
                uint32_t boff = offB2 + (uint32_t)(s * 32);
                ldsm4(sb + SM_FXH + boff, Bh);
                ldsm4(sb + SM_FXL + boff, Bl);
#pragma unroll
                for (int j = 0; j < 2; j++) {
                    mma16816(acc[j], Ah, Bh + 2 * j);
                    mma16816(acc[j], Ah, Bl + 2 * j);
                    mma16816(acc[j], Al, Bh + 2 * j);
                }
            }

            float* ob = out + (size_t)img * (2 * N_DIM * N_DIM) + which * (N_DIM * N_DIM);
            int nA = n0 + qt, nB = nA + 8;
#pragma unroll
            for (int j = 0; j < 2; j++) {
                int m = m0 + 8 * j + qr;
                *(float2*)(ob + nA * N_DIM + m) = make_float2(acc[j][0], acc[j][1]);
                *(float2*)(ob + nB * N_DIM + m) = make_float2(acc[j][2], acc[j][3]);
            }
        }
        // no loop-end barrier: the phase-A -> sync ordering next iteration
        // already separates this stage's tT reads from the next tT writes.
    }
}

extern "C" void kernel_launch(void* const* d_in, const int* in_sizes, int n_in,
                              void* d_out, int out_size) {
    const float* x  = (const float*)d_in[0];
    const float* xh = (const float*)d_in[1];
    const float* h  = (const float*)d_in[2];
    const float* Ww = (const float*)d_in[3];
    const float* Wb = (const float*)d_in[4];
    float* out = (float*)d_out;

    int sms = 148;
    cudaDeviceGetAttribute(&sms, cudaDevAttrMultiProcessorCount, 0);
    if (sms <= 0) sms = 148;

    cudaFuncSetAttribute(filt_mma, cudaFuncAttributeMaxDynamicSharedMemorySize, SM_TOTAL);

    setup_kernel<<<1, 256>>>(h, Ww, Wb);
    filt_mma<<<sms, 512, SM_TOTAL>>>(x, xh, out, sms);
}

// round 9
// speedup vs baseline: 1.1356x; 1.0198x over previous
#include <cuda_runtime.h>
#include <cuda_bf16.h>
#include <stdint.h>

#define A_DIM 128
#define N_DIM 64
#define H_DIM 1024
#define NJOBS 2048

#define ZSTR 136   // bf16 elems per z row   (272B: 8 ldmatrix rows cover 32 banks)
#define FSTR 136   // filterbank row stride
#define TSTR2 72   // tT row stride (144B, same property)

// Filterbanks, bf16 hi/lo, padded natural layout [row][stride]
__device__ __align__(16) unsigned short g_FyH[64 * FSTR];
__device__ __align__(16) unsigned short g_FyL[64 * FSTR];
__device__ __align__(16) unsigned short g_FxH[64 * FSTR];
__device__ __align__(16) unsigned short g_FxL[64 * FSTR];

// ---------------- helpers ----------------
__device__ __forceinline__ uint32_t smem_u32(const void* p) {
    uint32_t a;
    asm("{ .reg .u64 t; cvta.to.shared.u64 t, %1; cvt.u32.u64 %0, t; }" : "=r"(a) : "l"(p));
    return a;
}
// pack two f32 -> bf16x2; first arg lands in bits[15:0]
__device__ __forceinline__ uint32_t pkbf(float lo, float hi) {
    uint32_t r;
    asm("cvt.rn.bf16x2.f32 %0, %1, %2;" : "=r"(r) : "f"(hi), "f"(lo));
    return r;
}
__device__ __forceinline__ void ldsm4(uint32_t a, uint32_t* r) {
    asm volatile("ldmatrix.sync.aligned.m8n8.x4.shared.b16 {%0,%1,%2,%3}, [%4];"
                 : "=r"(r[0]), "=r"(r[1]), "=r"(r[2]), "=r"(r[3]) : "r"(a));
}
__device__ __forceinline__ void ldsm4t(uint32_t a, uint32_t* r) {
    asm volatile("ldmatrix.sync.aligned.m8n8.x4.trans.shared.b16 {%0,%1,%2,%3}, [%4];"
                 : "=r"(r[0]), "=r"(r[1]), "=r"(r[2]), "=r"(r[3]) : "r"(a));
}
__device__ __forceinline__ void mma16816(float* c, const uint32_t* a, const uint32_t* b) {
    asm volatile(
        "mma.sync.aligned.m16n8k16.row.col.f32.bf16.bf16.f32 "
        "{%0,%1,%2,%3}, {%4,%5,%6,%7}, {%8,%9}, {%0,%1,%2,%3};"
        : "+f"(c[0]), "+f"(c[1]), "+f"(c[2]), "+f"(c[3])
        : "r"(a[0]), "r"(a[1]), "r"(a[2]), "r"(a[3]), "r"(b[0]), "r"(b[1]));
}

// ---------------- setup: params -> split filterbanks ----------------
__global__ void setup_kernel(const float* __restrict__ h,
                             const float* __restrict__ Ww,
                             const float* __restrict__ Wb) {
    __shared__ float red[256];
    __shared__ float s_params[5];
    __shared__ float s_scal[5];
    int tid = threadIdx.x;

    for (int i = 0; i < 5; i++) {
        float p = 0.f;
        for (int j = tid; j < H_DIM; j += 256) p += Ww[i * H_DIM + j] * h[j];
        red[tid] = p;
        __syncthreads();
        for (int s = 128; s > 0; s >>= 1) {
            if (tid < s) red[tid] += red[tid + s];
            __syncthreads();
        }
        if (tid == 0) s_params[i] = red[0] + Wb[i];
        __syncthreads();
    }

    if (tid == 0) {
        float gtX = s_params[0];
        float gtY = s_params[1];
        float var = expf(s_params[2] + 1e-8f);
        float dd  = expf(s_params[3]) * (float)(A_DIM - 1) / (float)(N_DIM - 1);
        float gamma = expf(s_params[4]);
        s_scal[0] = (float)(A_DIM + 1) * (gtX + 1.f) * 0.5f;
        s_scal[1] = (float)(A_DIM + 1) * (gtY + 1.f) * 0.5f;
        s_scal[2] = dd;
        s_scal[3] = 1.f / (2.f * var);
        s_scal[4] = gamma;
    }
    __syncthreads();
    float gX = s_scal[0], gY = s_scal[1], dd = s_scal[2];
    float i2v = s_scal[3], gamma = s_scal[4];

    float sx = 0.f, sy = 0.f;
    for (int idx = tid; idx < N_DIM * A_DIM; idx += 256) {
        int n = idx >> 7, a = idx & 127;
        float off = ((float)n - (float)N_DIM * 0.5f - 0.5f) * dd;
        float da = (float)a - (gX + off);
        float db = (float)a - (gY + off);
        sx += expf(-da * da * i2v);
        sy += expf(-db * db * i2v);
    }
    red[tid] = sx;
    __syncthreads();
    for (int s = 128; s > 0; s >>= 1) { if (tid < s) red[tid] += red[tid + s]; __syncthreads(); }
    float sumX = red[0];
    __syncthreads();
    red[tid] = sy;
    __syncthreads();
    for (int s = 128; s > 0; s >>= 1) { if (tid < s) red[tid] += red[tid + s]; __syncthreads(); }
    float sumY = red[0];
    __syncthreads();

    float invX = 1.f / sumX;
    float invYg = gamma / sumY;

    for (int idx = tid; idx < N_DIM * A_DIM; idx += 256) {
        int n = idx >> 7, a = idx & 127;
        float off = ((float)n - (float)N_DIM * 0.5f - 0.5f) * dd;
        float da = (float)a - (gX + off);
        float db = (float)a - (gY + off);
        float fy = expf(-db * db * i2v) * invYg;  // gamma folded
        float fx = expf(-da * da * i2v) * invX;

        unsigned short yh = __bfloat16_as_ushort(__float2bfloat16(fy));
        float yhf = __uint_as_float(((uint32_t)yh) << 16);
        unsigned short yl = __bfloat16_as_ushort(__float2bfloat16(fy - yhf));
        unsigned short xhb = __bfloat16_as_ushort(__float2bfloat16(fx));
        float xhf = __uint_as_float(((uint32_t)xhb) << 16);
        unsigned short xl = __bfloat16_as_ushort(__float2bfloat16(fx - xhf));

        g_FyH[n * FSTR + a] = yh;
        g_FyL[n * FSTR + a] = yl;
        g_FxH[n * FSTR + a] = xhb;
        g_FxL[n * FSTR + a] = xl;
    }
}

// ---------------- SMEM layout (bytes) ----------------
#define SM_ZH   0
#define SM_ZL   34816
#define SM_TH   69632
#define SM_TL   88064
#define SM_FYH  106496
#define SM_FYL  123904
#define SM_FXH  141312
#define SM_FXL  158720
#define SM_TOTAL 176128

__global__ __launch_bounds__(512, 1)
void filt_mma(const float* __restrict__ x, const float* __restrict__ xh,
              float* __restrict__ out, int gridn) {
    extern __shared__ char sm[];
    int tid = threadIdx.x;
    int wid = tid >> 5, lane = tid & 31;
    int grp = lane >> 3, li = lane & 7;
    int qt = lane >> 2;          // t/4 : fragment row group
    int qr = (lane & 3) * 2;     // 2*(t%4) : fragment col pair

    // stage split filterbanks once per CTA
    {
        const uint4* s;
        uint4* d;
        s = (const uint4*)g_FyH; d = (uint4*)(sm + SM_FYH);
        for (int i = tid; i < 1088; i += 512) d[i] = s[i];
        s = (const uint4*)g_FyL; d = (uint4*)(sm + SM_FYL);
        for (int i = tid; i < 1088; i += 512) d[i] = s[i];
        s = (const uint4*)g_FxH; d = (uint4*)(sm + SM_FXH);
        for (int i = tid; i < 1088; i += 512) d[i] = s[i];
        s = (const uint4*)g_FxL; d = (uint4*)(sm + SM_FXL);
        for (int i = tid; i < 1088; i += 512) d[i] = s[i];
    }

    uint32_t sb = smem_u32(sm);

    // lane-constant ldmatrix byte offsets
    int radd = (grp >> 1) * 8;   // +8 rows for matrices 2,3
    int cadd = (grp & 1) * 8;    // +8 cols for matrices 1,3

    // ---- stage 1 mapping: 16 warps = 8 b-groups x 2 n-halves ----
    int bg = wid & 7;            // b-group
    int nh = wid >> 3;           // n-half (0/1)
    int b0w = bg * 16;
    uint32_t offA1 = (uint32_t)(((li + radd) * ZSTR + b0w + cadd) * 2);
    uint32_t offB1[2];
#pragma unroll
    for (int q = 0; q < 2; q++)
        offB1[q] = (uint32_t)(((nh * 32 + 16 * q + li + radd) * FSTR + cadd) * 2);

    // ---- stage 2 mapping: 16 warps = 4 n-strips x 4 m-quarters ----
    int n0 = (wid >> 2) * 16;
    int m0 = (wid & 3) * 16;
    uint32_t offA2 = (uint32_t)(((li + radd) * TSTR2 + n0 + cadd) * 2);
    uint32_t offB2 = (uint32_t)(((m0 + li + radd) * FSTR + cadd) * 2);

    __syncthreads();

    // register prefetch of first job's z tile
    float4 pre[8];
    {
        int job0 = blockIdx.x;
        const float* src = ((job0 >> 10) ? xh : x) + (size_t)(job0 & 1023) * (A_DIM * A_DIM);
        const float4* s4 = (const float4*)src;
#pragma unroll
        for (int i = 0; i < 8; i++) pre[i] = __ldg(s4 + tid + (i << 9));
    }

    for (int job = blockIdx.x; job < NJOBS; job += gridn) {
        int which = job >> 10;
        int img = job & 1023;

        // ---- 1. convert prefetched z regs -> smem bf16 hi/lo panels ----
        {
#pragma unroll
            for (int i = 0; i < 8; i++) {
                int e4 = tid + (i << 9);
                float4 v = pre[i];
                int e = e4 << 2;
                int a = e >> 7, b = e & 127;
                uint32_t hA = pkbf(v.x, v.y), hB = pkbf(v.z, v.w);
                float l0 = v.x - __uint_as_float(hA << 16);
                float l1 = v.y - __uint_as_float(hA & 0xFFFF0000u);
                float l2 = v.z - __uint_as_float(hB << 16);
                float l3 = v.w - __uint_as_float(hB & 0xFFFF0000u);
                uint32_t lA = pkbf(l0, l1), lB = pkbf(l2, l3);
                uint32_t boff = (uint32_t)((a * ZSTR + b) * 2);
                *(uint2*)(sm + SM_ZH + boff) = make_uint2(hA, hB);
                *(uint2*)(sm + SM_ZL + boff) = make_uint2(lA, lB);
            }
        }
        __syncthreads();

        // ---- issue prefetch for next job (latency hidden behind both MMA stages) ----
        {
            int nj = job + gridn;
            if (nj < NJOBS) {
                const float* nsrc = ((nj >> 10) ? xh : x) + (size_t)(nj & 1023) * (A_DIM * A_DIM);
                const float4* ns4 = (const float4*)nsrc;
#pragma unroll
                for (int i = 0; i < 8; i++) pre[i] = __ldg(ns4 + tid + (i << 9));
            }
        }

        // ---- 2. stage 1: tT[b][n] = sum_a z[a][b]*Fy[n][a] (3-term split) ----
        {
            float acc[4][4];
#pragma unroll
            for (int j = 0; j < 4; j++)
#pragma unroll
                for (int c = 0; c < 4; c++) acc[j][c] = 0.f;

#pragma unroll
            for (int s = 0; s < 8; s++) {
                uint32_t Ah[4], Al[4], Bh[8], Bl[8];
                uint32_t aoff = offA1 + (uint32_t)(s * 16 * ZSTR * 2);
                ldsm4t(sb + SM_ZH + aoff, Ah);
                ldsm4t(sb + SM_ZL + aoff, Al);
#pragma unroll
                for (int q = 0; q < 2; q++) {
                    uint32_t boff = offB1[q] + (uint32_t)(s * 32);
                    ldsm4(sb + SM_FYH + boff, Bh + 4 * q);
                    ldsm4(sb + SM_FYL + boff, Bl + 4 * q);
                }
                // term-major: consecutive MMAs hit different accumulators,
                // per-acc chain order (hh, hl, lh) unchanged.
#pragma unroll
                for (int j = 0; j < 4; j++) mma16816(acc[j], Ah, Bh + 2 * j);
#pragma unroll
                for (int j = 0; j < 4; j++) mma16816(acc[j], Ah, Bl + 2 * j);
#pragma unroll
                for (int j = 0; j < 4; j++) mma16816(acc[j], Al, Bh + 2 * j);
            }

            // write tT hi/lo
            int r0 = b0w + qt, r1 = r0 + 8;
#pragma unroll
            for (int j = 0; j < 4; j++) {
                int nj2 = nh * 32 + 8 * j + qr;
                uint32_t h01 = pkbf(acc[j][0], acc[j][1]);
                float d0 = acc[j][0] - __uint_as_float(h01 << 16);
                float d1 = acc[j][1] - __uint_as_float(h01 & 0xFFFF0000u);
                uint32_t l01 = pkbf(d0, d1);
                uint32_t h23 = pkbf(acc[j][2], acc[j][3]);
                float d2 = acc[j][2] - __uint_as_float(h23 << 16);
                float d3 = acc[j][3] - __uint_as_float(h23 & 0xFFFF0000u);
                uint32_t l23 = pkbf(d2, d3);
                *(uint32_t*)(sm + SM_TH + (r0 * TSTR2 + nj2) * 2) = h01;
                *(uint32_t*)(sm + SM_TL + (r0 * TSTR2 + nj2) * 2) = l01;
                *(uint32_t*)(sm + SM_TH + (r1 * TSTR2 + nj2) * 2) = h23;
                *(uint32_t*)(sm + SM_TL + (r1 * TSTR2 + nj2) * 2) = l23;
            }
        }
        __syncthreads();

        // ---- 3. stage 2: C[n][m] = sum_b t[n][b]*Fx[m][b] (3-term split) ----
        {
            float acc[2][4];
#pragma unroll
            for (int j = 0; j < 2; j++)
#pragma unroll
                for (int c = 0; c < 4; c++) acc[j][c] = 0.f;

#pragma unroll
            for (int s = 0; s < 8; s++) {
                uint32_t Ah[4], Al[4], Bh[4], Bl[4];
                uint32_t aoff = offA2 + (uint32_t)(s * 16 * TSTR2 * 2);
                ldsm4t(sb + SM_TH + aoff, Ah);
                ldsm4t(sb + SM_TL + aoff, Al);
                uint32_t boff = offB2 + (uint32_t)(s * 32);
                ldsm4(sb + SM_FXH + boff, Bh);
                ldsm4(sb + SM_FXL + boff, Bl);
                // term-major interleave across the two accumulators
#pragma unroll
                for (int j = 0; j < 2; j++) mma16816(acc[j], Ah, Bh + 2 * j);
#pragma unroll
                for (int j = 0; j < 2; j++) mma16816(acc[j], Ah, Bl + 2 * j);
#pragma unroll
                for (int j = 0; j < 2; j++) mma16816(acc[j], Al, Bh + 2 * j);
            }

            float* ob = out + (size_t)img * (2 * N_DIM * N_DIM) + which * (N_DIM * N_DIM);
            int nA = n0 + qt, nB = nA + 8;
#pragma unroll
            for (int j = 0; j < 2; j++) {
                int m = m0 + 8 * j + qr;
                *(float2*)(ob + nA * N_DIM + m) = make_float2(acc[j][0], acc[j][1]);
                *(float2*)(ob + nB * N_DIM + m) = make_float2(acc[j][2], acc[j][3]);
            }
        }
        // no loop-end barrier: the phase-A -> sync ordering next iteration
        // already separates this stage's tT reads from the next tT writes.
    }
}

extern "C" void kernel_launch(void* const* d_in, const int* in_sizes, int n_in,
                              void* d_out, int out_size) {
    const float* x  = (const float*)d_in[0];
    const float* xh = (const float*)d_in[1];
    const float* h  = (const float*)d_in[2];
    const float* Ww = (const float*)d_in[3];
    const float* Wb = (const float*)d_in[4];
    float* out = (float*)d_out;

    int sms = 148;
    cudaDeviceGetAttribute(&sms, cudaDevAttrMultiProcessorCount, 0);
    if (sms <= 0) sms = 148;

    cudaFuncSetAttribute(filt_mma, cudaFuncAttributeMaxDynamicSharedMemorySize, SM_TOTAL);

    setup_kernel<<<1, 256>>>(h, Ww, Wb);
    filt_mma<<<sms, 512, SM_TOTAL>>>(x, xh, out, sms);
}

// round 10
// speedup vs baseline: 1.2384x; 1.0905x over previous
#include <cuda_runtime.h>
#include <cuda_bf16.h>
#include <stdint.h>

#define A_DIM 128
#define N_DIM 64
#define H_DIM 1024
#define NJOBS 2048

#define ZSTR 136   // bf16 elems per z row   (272B: 8 ldmatrix rows cover 32 banks)
#define FSTR 136   // filterbank row stride
#define TSTR2 72   // tT row stride (144B, same property)

// ---------------- helpers ----------------
__device__ __forceinline__ uint32_t smem_u32(const void* p) {
    uint32_t a;
    asm("{ .reg .u64 t; cvta.to.shared.u64 t, %1; cvt.u32.u64 %0, t; }" : "=r"(a) : "l"(p));
    return a;
}
// pack two f32 -> bf16x2; first arg lands in bits[15:0]
__device__ __forceinline__ uint32_t pkbf(float lo, float hi) {
    uint32_t r;
    asm("cvt.rn.bf16x2.f32 %0, %1, %2;" : "=r"(r) : "f"(hi), "f"(lo));
    return r;
}
__device__ __forceinline__ void ldsm4(uint32_t a, uint32_t* r) {
    asm volatile("ldmatrix.sync.aligned.m8n8.x4.shared.b16 {%0,%1,%2,%3}, [%4];"
                 : "=r"(r[0]), "=r"(r[1]), "=r"(r[2]), "=r"(r[3]) : "r"(a));
}
__device__ __forceinline__ void ldsm4t(uint32_t a, uint32_t* r) {
    asm volatile("ldmatrix.sync.aligned.m8n8.x4.trans.shared.b16 {%0,%1,%2,%3}, [%4];"
                 : "=r"(r[0]), "=r"(r[1]), "=r"(r[2]), "=r"(r[3]) : "r"(a));
}
__device__ __forceinline__ void mma16816(float* c, const uint32_t* a, const uint32_t* b) {
    asm volatile(
        "mma.sync.aligned.m16n8k16.row.col.f32.bf16.bf16.f32 "
        "{%0,%1,%2,%3}, {%4,%5,%6,%7}, {%8,%9}, {%0,%1,%2,%3};"
        : "+f"(c[0]), "+f"(c[1]), "+f"(c[2]), "+f"(c[3])
        : "r"(a[0]), "r"(a[1]), "r"(a[2]), "r"(a[3]), "r"(b[0]), "r"(b[1]));
}

// ---------------- SMEM layout (bytes) ----------------
#define SM_ZH   0
#define SM_ZL   34816
#define SM_TH   69632
#define SM_TL   88064
#define SM_FYH  106496
#define SM_FYL  123904
#define SM_FXH  141312
#define SM_FXL  158720
#define SM_TOTAL 176128

__global__ __launch_bounds__(512, 1)
void filt_mma(const float* __restrict__ x, const float* __restrict__ xh,
              const float* __restrict__ hvec, const float* __restrict__ Ww,
              const float* __restrict__ Wb,
              float* __restrict__ out, int gridn) {
    extern __shared__ char sm[];
    __shared__ float red[512];
    __shared__ float s_scal[8];

    int tid = threadIdx.x;
    int wid = tid >> 5, lane = tid & 31;
    int grp = lane >> 3, li = lane & 7;
    int qt = lane >> 2;          // t/4 : fragment row group
    int qr = (lane & 3) * 2;     // 2*(t%4) : fragment col pair

    // ======== per-CTA setup: params -> split filterbanks in smem ========
    {
        // 5-element readout: params[i] = dot(Ww[i,:], h[0,:]) + Wb[i]
        float params[5];
        for (int i = 0; i < 5; i++) {
            float p = 0.f;
            for (int j = tid; j < H_DIM; j += 512) p += __ldg(Ww + i * H_DIM + j) * __ldg(hvec + j);
            red[tid] = p;
            __syncthreads();
            for (int s = 256; s > 0; s >>= 1) {
                if (tid < s) red[tid] += red[tid + s];
                __syncthreads();
            }
            params[i] = red[0] + __ldg(Wb + i);
            __syncthreads();
        }

        if (tid == 0) {
            float var = expf(params[2] + 1e-8f);
            float dd  = expf(params[3]) * (float)(A_DIM - 1) / (float)(N_DIM - 1);
            s_scal[0] = (float)(A_DIM + 1) * (params[0] + 1.f) * 0.5f;  // g_X
            s_scal[1] = (float)(A_DIM + 1) * (params[1] + 1.f) * 0.5f;  // g_Y
            s_scal[2] = dd;
            s_scal[3] = 1.f / (2.f * var);
            s_scal[4] = expf(params[4]);                                 // gamma
        }
        __syncthreads();
        float gX = s_scal[0], gY = s_scal[1], dd = s_scal[2];
        float i2v = s_scal[3], gamma = s_scal[4];

        // pass 1: global sums
        float sx = 0.f, sy = 0.f;
        for (int idx = tid; idx < N_DIM * A_DIM; idx += 512) {
            int n = idx >> 7, a = idx & 127;
            float off = ((float)n - (float)N_DIM * 0.5f - 0.5f) * dd;
            float da = (float)a - (gX + off);
            float db = (float)a - (gY + off);
            sx += expf(-da * da * i2v);
            sy += expf(-db * db * i2v);
        }
        red[tid] = sx;
        __syncthreads();
        for (int s = 256; s > 0; s >>= 1) { if (tid < s) red[tid] += red[tid + s]; __syncthreads(); }
        float invX = 1.f / red[0];
        __syncthreads();
        red[tid] = sy;
        __syncthreads();
        for (int s = 256; s > 0; s >>= 1) { if (tid < s) red[tid] += red[tid + s]; __syncthreads(); }
        float invYg = gamma / red[0];
        __syncthreads();

        // pass 2: split + store into smem filterbank panels
        for (int idx = tid; idx < N_DIM * A_DIM; idx += 512) {
            int n = idx >> 7, a = idx & 127;
            float off = ((float)n - (float)N_DIM * 0.5f - 0.5f) * dd;
            float da = (float)a - (gX + off);
            float db = (float)a - (gY + off);
            float fy = expf(-db * db * i2v) * invYg;  // gamma folded
            float fx = expf(-da * da * i2v) * invX;

            unsigned short yh = __bfloat16_as_ushort(__float2bfloat16(fy));
            float yhf = __uint_as_float(((uint32_t)yh) << 16);
            unsigned short yl = __bfloat16_as_ushort(__float2bfloat16(fy - yhf));
            unsigned short xhb = __bfloat16_as_ushort(__float2bfloat16(fx));
            float xhf = __uint_as_float(((uint32_t)xhb) << 16);
            unsigned short xl = __bfloat16_as_ushort(__float2bfloat16(fx - xhf));

            uint32_t o = (uint32_t)((n * FSTR + a) * 2);
            *(unsigned short*)(sm + SM_FYH + o) = yh;
            *(unsigned short*)(sm + SM_FYL + o) = yl;
            *(unsigned short*)(sm + SM_FXH + o) = xhb;
            *(unsigned short*)(sm + SM_FXL + o) = xl;
        }
    }

    uint32_t sb = smem_u32(sm);

    // lane-constant ldmatrix byte offsets
    int radd = (grp >> 1) * 8;   // +8 rows for matrices 2,3
    int cadd = (grp & 1) * 8;    // +8 cols for matrices 1,3

    // ---- stage 1 mapping: 16 warps = 8 b-groups x 2 n-halves ----
    int bg = wid & 7;            // b-group
    int nh = wid >> 3;           // n-half (0/1)
    int b0w = bg * 16;
    uint32_t offA1 = (uint32_t)(((li + radd) * ZSTR + b0w + cadd) * 2);
    uint32_t offB1[2];
#pragma unroll
    for (int q = 0; q < 2; q++)
        offB1[q] = (uint32_t)(((nh * 32 + 16 * q + li + radd) * FSTR + cadd) * 2);

    // ---- stage 2 mapping: 16 warps = 4 n-strips x 4 m-quarters ----
    int n0 = (wid >> 2) * 16;
    int m0 = (wid & 3) * 16;
    uint32_t offA2 = (uint32_t)(((li + radd) * TSTR2 + n0 + cadd) * 2);
    uint32_t offB2 = (uint32_t)(((m0 + li + radd) * FSTR + cadd) * 2);

    // convert-and-store of a register-held z tile -> smem bf16 hi/lo panels
    auto phaseA = [&](const float4* pre) {
#pragma unroll
        for (int i = 0; i < 8; i++) {
            int e4 = tid + (i << 9);
            float4 v = pre[i];
            int e = e4 << 2;
            int a = e >> 7, b = e & 127;
            uint32_t hA = pkbf(v.x, v.y), hB = pkbf(v.z, v.w);
            float l0 = v.x - __uint_as_float(hA << 16);
            float l1 = v.y - __uint_as_float(hA & 0xFFFF0000u);
            float l2 = v.z - __uint_as_float(hB << 16);
            float l3 = v.w - __uint_as_float(hB & 0xFFFF0000u);
            uint32_t lA = pkbf(l0, l1), lB = pkbf(l2, l3);
            uint32_t boff = (uint32_t)((a * ZSTR + b) * 2);
            *(uint2*)(sm + SM_ZH + boff) = make_uint2(hA, hB);
            *(uint2*)(sm + SM_ZL + boff) = make_uint2(lA, lB);
        }
    };
    auto ldz = [&](int job, float4* pre) {
        const float* src = ((job >> 10) ? xh : x) + (size_t)(job & 1023) * (A_DIM * A_DIM);
        const float4* s4 = (const float4*)src;
#pragma unroll
        for (int i = 0; i < 8; i++) pre[i] = __ldg(s4 + tid + (i << 9));
    };

    // prologue: z(job0) into smem, z(job1) into regs
    float4 pre[8];
    ldz(blockIdx.x, pre);
    phaseA(pre);
    if (blockIdx.x + gridn < NJOBS) ldz(blockIdx.x + gridn, pre);
    __syncthreads();  // z + filterbanks visible

    for (int job = blockIdx.x; job < NJOBS; job += gridn) {
        int which = job >> 10;
        int img = job & 1023;

        // ---- stage 1: tT[b][n] = sum_a z[a][b]*Fy[n][a] (3-term split) ----
        {
            float acc[4][4];
#pragma unroll
            for (int j = 0; j < 4; j++)
#pragma unroll
                for (int c = 0; c < 4; c++) acc[j][c] = 0.f;

#pragma unroll
            for (int s = 0; s < 8; s++) {
                uint32_t Ah[4], Al[4], Bh[8], Bl[8];
                uint32_t aoff = offA1 + (uint32_t)(s * 16 * ZSTR * 2);
                ldsm4t(sb + SM_ZH + aoff, Ah);
                ldsm4t(sb + SM_ZL + aoff, Al);
#pragma unroll
                for (int q = 0; q < 2; q++) {
                    uint32_t boff = offB1[q] + (uint32_t)(s * 32);
                    ldsm4(sb + SM_FYH + boff, Bh + 4 * q);
                    ldsm4(sb + SM_FYL + boff, Bl + 4 * q);
                }
#pragma unroll
                for (int j = 0; j < 4; j++) mma16816(acc[j], Ah, Bh + 2 * j);
#pragma unroll
                for (int j = 0; j < 4; j++) mma16816(acc[j], Ah, Bl + 2 * j);
#pragma unroll
                for (int j = 0; j < 4; j++) mma16816(acc[j], Al, Bh + 2 * j);
            }

            // write tT hi/lo
            int r0 = b0w + qt, r1 = r0 + 8;
#pragma unroll
            for (int j = 0; j < 4; j++) {
                int nj2 = nh * 32 + 8 * j + qr;
                uint32_t h01 = pkbf(acc[j][0], acc[j][1]);
                float d0 = acc[j][0] - __uint_as_float(h01 << 16);
                float d1 = acc[j][1] - __uint_as_float(h01 & 0xFFFF0000u);
                uint32_t l01 = pkbf(d0, d1);
                uint32_t h23 = pkbf(acc[j][2], acc[j][3]);
                float d2 = acc[j][2] - __uint_as_float(h23 << 16);
                float d3 = acc[j][3] - __uint_as_float(h23 & 0xFFFF0000u);
                uint32_t l23 = pkbf(d2, d3);
                *(uint32_t*)(sm + SM_TH + (r0 * TSTR2 + nj2) * 2) = h01;
                *(uint32_t*)(sm + SM_TL + (r0 * TSTR2 + nj2) * 2) = l01;
                *(uint32_t*)(sm + SM_TH + (r1 * TSTR2 + nj2) * 2) = h23;
                *(uint32_t*)(sm + SM_TL + (r1 * TSTR2 + nj2) * 2) = l23;
            }
        }
        __syncthreads();  // tT ready; z buffer free

        // ---- phase A for next job (hidden under stage 2), then refill pre ----
        if (job + gridn < NJOBS) {
            phaseA(pre);
            if (job + 2 * gridn < NJOBS) ldz(job + 2 * gridn, pre);
        }

        // ---- stage 2: C[n][m] = sum_b t[n][b]*Fx[m][b] (3-term split) ----
        {
            float acc[2][4];
#pragma unroll
            for (int j = 0; j < 2; j++)
#pragma unroll
                for (int c = 0; c < 4; c++) acc[j][c] = 0.f;

#pragma unroll
            for (int s = 0; s < 8; s++) {
                uint32_t Ah[4], Al[4], Bh[4], Bl[4];
                uint32_t aoff = offA2 + (uint32_t)(s * 16 * TSTR2 * 2);
                ldsm4t(sb + SM_TH + aoff, Ah);
                ldsm4t(sb + SM_TL + aoff, Al);
                uint32_t boff = offB2 + (uint32_t)(s * 32);
                ldsm4(sb + SM_FXH + boff, Bh);
                ldsm4(sb + SM_FXL + boff, Bl);
#pragma unroll
                for (int j = 0; j < 2; j++) mma16816(acc[j], Ah, Bh + 2 * j);
#pragma unroll
                for (int j = 0; j < 2; j++) mma16816(acc[j], Ah, Bl + 2 * j);
#pragma unroll
                for (int j = 0; j < 2; j++) mma16816(acc[j], Al, Bh + 2 * j);
            }

            float* ob = out + (size_t)img * (2 * N_DIM * N_DIM) + which * (N_DIM * N_DIM);
            int nA = n0 + qt, nB = nA + 8;
#pragma unroll
            for (int j = 0; j < 2; j++) {
                int m = m0 + 8 * j + qr;
                *(float2*)(ob + nA * N_DIM + m) = make_float2(acc[j][0], acc[j][1]);
                *(float2*)(ob + nB * N_DIM + m) = make_float2(acc[j][2], acc[j][3]);
            }
        }
        __syncthreads();  // next z visible; tT free for next stage 1
    }
}

extern "C" void kernel_launch(void* const* d_in, const int* in_sizes, int n_in,
                              void* d_out, int out_size) {
    const float* x  = (const float*)d_in[0];
    const float* xh = (const float*)d_in[1];
    const float* h  = (const float*)d_in[2];
    const float* Ww = (const float*)d_in[3];
    const float* Wb = (const float*)d_in[4];
    float* out = (float*)d_out;

    int sms = 148;
    cudaDeviceGetAttribute(&sms, cudaDevAttrMultiProcessorCount, 0);
    if (sms <= 0) sms = 148;

    cudaFuncSetAttribute(filt_mma, cudaFuncAttributeMaxDynamicSharedMemorySize, SM_TOTAL);

    filt_mma<<<sms, 512, SM_TOTAL>>>(x, xh, h, Ww, Wb, out, sms);
}

// round 11
// speedup vs baseline: 1.3948x; 1.1262x over previous
#include <cuda_runtime.h>
#include <cuda_bf16.h>
#include <stdint.h>

#define A_DIM 128
#define N_DIM 64
#define H_DIM 1024
#define NJOBS 2048

#define ZSTR 136   // bf16 elems per z row
#define FSTR 136   // filterbank row stride
#define TSTR2 72   // tT row stride

// ---------------- helpers ----------------
__device__ __forceinline__ uint32_t smem_u32(const void* p) {
    uint32_t a;
    asm("{ .reg .u64 t; cvta.to.shared.u64 t, %1; cvt.u32.u64 %0, t; }" : "=r"(a) : "l"(p));
    return a;
}
__device__ __forceinline__ uint32_t pkbf(float lo, float hi) {
    uint32_t r;
    asm("cvt.rn.bf16x2.f32 %0, %1, %2;" : "=r"(r) : "f"(hi), "f"(lo));
    return r;
}
__device__ __forceinline__ void ldsm4(uint32_t a, uint32_t* r) {
    asm volatile("ldmatrix.sync.aligned.m8n8.x4.shared.b16 {%0,%1,%2,%3}, [%4];"
                 : "=r"(r[0]), "=r"(r[1]), "=r"(r[2]), "=r"(r[3]) : "r"(a));
}
__device__ __forceinline__ void ldsm4t(uint32_t a, uint32_t* r) {
    asm volatile("ldmatrix.sync.aligned.m8n8.x4.trans.shared.b16 {%0,%1,%2,%3}, [%4];"
                 : "=r"(r[0]), "=r"(r[1]), "=r"(r[2]), "=r"(r[3]) : "r"(a));
}
__device__ __forceinline__ void mma16816(float* c, const uint32_t* a, const uint32_t* b) {
    asm volatile(
        "mma.sync.aligned.m16n8k16.row.col.f32.bf16.bf16.f32 "
        "{%0,%1,%2,%3}, {%4,%5,%6,%7}, {%8,%9}, {%0,%1,%2,%3};"
        : "+f"(c[0]), "+f"(c[1]), "+f"(c[2]), "+f"(c[3])
        : "r"(a[0]), "r"(a[1]), "r"(a[2]), "r"(a[3]), "r"(b[0]), "r"(b[1]));
}

// ---------------- SMEM layout (bytes) ----------------
#define SM_ZH   0
#define SM_ZL   34816
#define SM_TH   69632
#define SM_TL   88064
#define SM_FYH  106496
#define SM_FYL  123904
#define SM_FXH  141312
#define SM_FXL  158720
#define SM_TOTAL 176128

__global__ __launch_bounds__(512, 1)
void filt_mma(const float* __restrict__ x, const float* __restrict__ xh,
              const float* __restrict__ hvec, const float* __restrict__ Ww,
              const float* __restrict__ Wb,
              float* __restrict__ out, int gridn) {
    extern __shared__ char sm[];
    __shared__ float s_par[5];
    __shared__ float s_red[32];
    __shared__ float s_inv[2];

    int tid = threadIdx.x;
    int wid = tid >> 5, lane = tid & 31;
    int grp = lane >> 3, li = lane & 7;
    int qt = lane >> 2;
    int qr = (lane & 3) * 2;

    // ======== prologue: params via warp-shuffle reductions ========
    if (wid < 5) {
        float p = 0.f;
        for (int j = lane; j < H_DIM; j += 32)
            p += __ldg(Ww + wid * H_DIM + j) * __ldg(hvec + j);
#pragma unroll
        for (int o = 16; o; o >>= 1) p += __shfl_xor_sync(0xFFFFFFFFu, p, o);
        if (lane == 0) s_par[wid] = p + __ldg(Wb + wid);
    }
    __syncthreads();

    float gX, gY, dd, i2v, gamma;
    {
        float var = expf(s_par[2] + 1e-8f);
        dd = expf(s_par[3]) * (float)(A_DIM - 1) / (float)(N_DIM - 1);
        gamma = expf(s_par[4]);
        gX = (float)(A_DIM + 1) * (s_par[0] + 1.f) * 0.5f;
        gY = (float)(A_DIM + 1) * (s_par[1] + 1.f) * 0.5f;
        i2v = 1.f / (2.f * var);
    }

    // pass 1: global sums (per-warp shfl, then warp 0)
    {
        float sx = 0.f, sy = 0.f;
        for (int idx = tid; idx < N_DIM * A_DIM; idx += 512) {
            int n = idx >> 7, a = idx & 127;
            float off = ((float)n - (float)N_DIM * 0.5f - 0.5f) * dd;
            float da = (float)a - (gX + off);
            float db = (float)a - (gY + off);
            sx += expf(-da * da * i2v);
            sy += expf(-db * db * i2v);
        }
#pragma unroll
        for (int o = 16; o; o >>= 1) {
            sx += __shfl_xor_sync(0xFFFFFFFFu, sx, o);
            sy += __shfl_xor_sync(0xFFFFFFFFu, sy, o);
        }
        if (lane == 0) { s_red[wid] = sx; s_red[16 + wid] = sy; }
        __syncthreads();
        if (wid == 0) {
            float vx = (lane < 16) ? s_red[lane] : 0.f;
            float vy = (lane < 16) ? s_red[16 + lane] : 0.f;
#pragma unroll
            for (int o = 16; o; o >>= 1) {
                vx += __shfl_xor_sync(0xFFFFFFFFu, vx, o);
                vy += __shfl_xor_sync(0xFFFFFFFFu, vy, o);
            }
            if (lane == 0) { s_inv[0] = 1.f / vx; s_inv[1] = gamma / vy; }
        }
        __syncthreads();
    }
    float invX = s_inv[0], invYg = s_inv[1];

    // pass 2: split filterbanks into smem panels
    for (int idx = tid; idx < N_DIM * A_DIM; idx += 512) {
        int n = idx >> 7, a = idx & 127;
        float off = ((float)n - (float)N_DIM * 0.5f - 0.5f) * dd;
        float da = (float)a - (gX + off);
        float db = (float)a - (gY + off);
        float fy = expf(-db * db * i2v) * invYg;
        float fx = expf(-da * da * i2v) * invX;

        unsigned short yh = __bfloat16_as_ushort(__float2bfloat16(fy));
        float yhf = __uint_as_float(((uint32_t)yh) << 16);
        unsigned short yl = __bfloat16_as_ushort(__float2bfloat16(fy - yhf));
        unsigned short xhb = __bfloat16_as_ushort(__float2bfloat16(fx));
        float xhf = __uint_as_float(((uint32_t)xhb) << 16);
        unsigned short xl = __bfloat16_as_ushort(__float2bfloat16(fx - xhf));

        uint32_t o = (uint32_t)((n * FSTR + a) * 2);
        *(unsigned short*)(sm + SM_FYH + o) = yh;
        *(unsigned short*)(sm + SM_FYL + o) = yl;
        *(unsigned short*)(sm + SM_FXH + o) = xhb;
        *(unsigned short*)(sm + SM_FXL + o) = xl;
    }

    uint32_t sb = smem_u32(sm);
    int radd = (grp >> 1) * 8;
    int cadd = (grp & 1) * 8;

    bool is_compute = (wid < 8);
    int ltid = tid - 256;  // loader thread index (wid>=8)

    // loader: load z(job) -> smem bf16 hi/lo panels (256 threads)
    auto ldz = [&](int job) {
        const float* src = ((job >> 10) ? xh : x) + (size_t)(job & 1023) * (A_DIM * A_DIM);
        const float4* s4 = (const float4*)src;
#pragma unroll
        for (int i = 0; i < 16; i++) {
            int e4 = ltid + (i << 8);
            float4 v = __ldg(s4 + e4);
            int e = e4 << 2;
            int a = e >> 7, b = e & 127;
            uint32_t hA = pkbf(v.x, v.y), hB = pkbf(v.z, v.w);
            float l0 = v.x - __uint_as_float(hA << 16);
            float l1 = v.y - __uint_as_float(hA & 0xFFFF0000u);
            float l2 = v.z - __uint_as_float(hB << 16);
            float l3 = v.w - __uint_as_float(hB & 0xFFFF0000u);
            uint32_t lA = pkbf(l0, l1), lB = pkbf(l2, l3);
            uint32_t boff = (uint32_t)((a * ZSTR + b) * 2);
            *(uint2*)(sm + SM_ZH + boff) = make_uint2(hA, hB);
            *(uint2*)(sm + SM_ZL + boff) = make_uint2(lA, lB);
        }
    };

    // ---- compute-warp mappings (wid < 8) ----
    // stage 1: 8 warps = 4 b-groups (32 wide) x 2 n-halves (32 wide)
    int bg2 = wid & 3, nhh = wid >> 2;
    int b0 = bg2 * 32;
    uint32_t offA1p0 = (uint32_t)(((li + radd) * ZSTR + b0 + cadd) * 2);
    uint32_t offA1p1 = offA1p0 + 32;
    uint32_t offB1[2];
#pragma unroll
    for (int q = 0; q < 2; q++)
        offB1[q] = (uint32_t)(((nhh * 32 + 16 * q + li + radd) * FSTR + cadd) * 2);

    // stage 2: 8 warps = 4 n-strips (16) x 2 m-halves (32)
    int n0 = (wid >> 1) * 16;
    int m0 = (wid & 1) * 32;
    uint32_t offA2 = (uint32_t)(((li + radd) * TSTR2 + n0 + cadd) * 2);
    uint32_t offB2[2];
#pragma unroll
    for (int q = 0; q < 2; q++)
        offB2[q] = (uint32_t)(((m0 + 16 * q + li + radd) * FSTR + cadd) * 2);

    // prime z(job0) — loaders only
    if (!is_compute) ldz(blockIdx.x);
    __syncthreads();  // panels + z(0) visible

    for (int job = blockIdx.x; job < NJOBS; job += gridn) {
        int which = job >> 10;
        int img = job & 1023;

        // ---- stage 1 (compute warps): tT[b][n] = sum_a z[a][b]*Fy[n][a] ----
        if (is_compute) {
            float acc[2][4][4];
#pragma unroll
            for (int p = 0; p < 2; p++)
#pragma unroll
                for (int j = 0; j < 4; j++)
#pragma unroll
                    for (int c = 0; c < 4; c++) acc[p][j][c] = 0.f;

#pragma unroll
            for (int s = 0; s < 8; s++) {
                uint32_t Ah[2][4], Al[2][4], Bh[8], Bl[8];
                uint32_t abase = (uint32_t)(s * 16 * ZSTR * 2);
                ldsm4t(sb + SM_ZH + offA1p0 + abase, Ah[0]);
                ldsm4t(sb + SM_ZH + offA1p1 + abase, Ah[1]);
                ldsm4t(sb + SM_ZL + offA1p0 + abase, Al[0]);
                ldsm4t(sb + SM_ZL + offA1p1 + abase, Al[1]);
#pragma unroll
                for (int q = 0; q < 2; q++) {
                    uint32_t boff = offB1[q] + (uint32_t)(s * 32);
                    ldsm4(sb + SM_FYH + boff, Bh + 4 * q);
                    ldsm4(sb + SM_FYL + boff, Bl + 4 * q);
                }
#pragma unroll
                for (int p = 0; p < 2; p++)
#pragma unroll
                    for (int j = 0; j < 4; j++) mma16816(acc[p][j], Ah[p], Bh + 2 * j);
#pragma unroll
                for (int p = 0; p < 2; p++)
#pragma unroll
                    for (int j = 0; j < 4; j++) mma16816(acc[p][j], Ah[p], Bl + 2 * j);
#pragma unroll
                for (int p = 0; p < 2; p++)
#pragma unroll
                    for (int j = 0; j < 4; j++) mma16816(acc[p][j], Al[p], Bh + 2 * j);
            }

            // write tT hi/lo
#pragma unroll
            for (int p = 0; p < 2; p++) {
                int r0 = b0 + 16 * p + qt, r1 = r0 + 8;
#pragma unroll
                for (int j = 0; j < 4; j++) {
                    int nj2 = nhh * 32 + 8 * j + qr;
                    uint32_t h01 = pkbf(acc[p][j][0], acc[p][j][1]);
                    float d0 = acc[p][j][0] - __uint_as_float(h01 << 16);
                    float d1 = acc[p][j][1] - __uint_as_float(h01 & 0xFFFF0000u);
                    uint32_t l01 = pkbf(d0, d1);
                    uint32_t h23 = pkbf(acc[p][j][2], acc[p][j][3]);
                    float d2 = acc[p][j][2] - __uint_as_float(h23 << 16);
                    float d3 = acc[p][j][3] - __uint_as_float(h23 & 0xFFFF0000u);
                    uint32_t l23 = pkbf(d2, d3);
                    *(uint32_t*)(sm + SM_TH + (r0 * TSTR2 + nj2) * 2) = h01;
                    *(uint32_t*)(sm + SM_TL + (r0 * TSTR2 + nj2) * 2) = l01;
                    *(uint32_t*)(sm + SM_TH + (r1 * TSTR2 + nj2) * 2) = h23;
                    *(uint32_t*)(sm + SM_TL + (r1 * TSTR2 + nj2) * 2) = l23;
                }
            }
        }
        __syncthreads();  // tT ready; z buffer free

        if (!is_compute) {
            // ---- loaders: fetch next job's z while compute runs stage 2 ----
            if (job + gridn < NJOBS) ldz(job + gridn);
        } else {
            // ---- stage 2: C[n][m] = sum_b t[n][b]*Fx[m][b] ----
            float acc[4][4];
#pragma unroll
            for (int j = 0; j < 4; j++)
#pragma unroll
                for (int c = 0; c < 4; c++) acc[j][c] = 0.f;

#pragma unroll
            for (int s = 0; s < 8; s++) {
                uint32_t Ah[4], Al[4], Bh[8], Bl[8];
                uint32_t aoff = offA2 + (uint32_t)(s * 16 * TSTR2 * 2);
                ldsm4t(sb + SM_TH + aoff, Ah);
                ldsm4t(sb + SM_TL + aoff, Al);
#pragma unroll
                for (int q = 0; q < 2; q++) {
                    uint32_t boff = offB2[q] + (uint32_t)(s * 32);
                    ldsm4(sb + SM_FXH + boff, Bh + 4 * q);
                    ldsm4(sb + SM_FXL + boff, Bl + 4 * q);
                }
#pragma unroll
                for (int j = 0; j < 4; j++) mma16816(acc[j], Ah, Bh + 2 * j);
#pragma unroll
                for (int j = 0; j < 4; j++) mma16816(acc[j], Ah, Bl + 2 * j);
#pragma unroll
                for (int j = 0; j < 4; j++) mma16816(acc[j], Al, Bh + 2 * j);
            }

            float* ob = out + (size_t)img * (2 * N_DIM * N_DIM) + which * (N_DIM * N_DIM);
            int nA = n0 + qt, nB = nA + 8;
#pragma unroll
            for (int j = 0; j < 4; j++) {
                int m = m0 + 8 * j + qr;
                *(float2*)(ob + nA * N_DIM + m) = make_float2(acc[j][0], acc[j][1]);
                *(float2*)(ob + nB * N_DIM + m) = make_float2(acc[j][2], acc[j][3]);
            }
        }
        __syncthreads();  // next z visible; tT free
    }
}

extern "C" void kernel_launch(void* const* d_in, const int* in_sizes, int n_in,
                              void* d_out, int out_size) {
    const float* x  = (const float*)d_in[0];
    const float* xh = (const float*)d_in[1];
    const float* h  = (const float*)d_in[2];
    const float* Ww = (const float*)d_in[3];
    const float* Wb = (const float*)d_in[4];
    float* out = (float*)d_out;

    int sms = 148;
    cudaDeviceGetAttribute(&sms, cudaDevAttrMultiProcessorCount, 0);
    if (sms <= 0) sms = 148;

    cudaFuncSetAttribute(filt_mma, cudaFuncAttributeMaxDynamicSharedMemorySize, SM_TOTAL);

    filt_mma<<<sms, 512, SM_TOTAL>>>(x, xh, h, Ww, Wb, out, sms);
}

// round 12
// speedup vs baseline: 1.7951x; 1.2870x over previous
#include <cuda_runtime.h>
#include <cuda_fp16.h>
#include <stdint.h>

#define A_DIM 128
#define N_DIM 64
#define H_DIM 1024
#define NJOBS 2048

#define ZSTR 136   // fp16 elems per z row
#define FSTR 136   // filterbank row stride
#define TSTR2 72   // tT row stride

// ---------------- helpers ----------------
__device__ __forceinline__ uint32_t smem_u32(const void* p) {
    uint32_t a;
    asm("{ .reg .u64 t; cvta.to.shared.u64 t, %1; cvt.u32.u64 %0, t; }" : "=r"(a) : "l"(p));
    return a;
}
// pack two f32 -> f16x2; first arg lands in bits[15:0]
__device__ __forceinline__ uint32_t pkhf(float lo, float hi) {
    uint32_t r;
    asm("cvt.rn.f16x2.f32 %0, %1, %2;" : "=r"(r) : "f"(hi), "f"(lo));
    return r;
}
__device__ __forceinline__ void ldsm4(uint32_t a, uint32_t* r) {
    asm volatile("ldmatrix.sync.aligned.m8n8.x4.shared.b16 {%0,%1,%2,%3}, [%4];"
                 : "=r"(r[0]), "=r"(r[1]), "=r"(r[2]), "=r"(r[3]) : "r"(a));
}
__device__ __forceinline__ void ldsm4t(uint32_t a, uint32_t* r) {
    asm volatile("ldmatrix.sync.aligned.m8n8.x4.trans.shared.b16 {%0,%1,%2,%3}, [%4];"
                 : "=r"(r[0]), "=r"(r[1]), "=r"(r[2]), "=r"(r[3]) : "r"(a));
}
__device__ __forceinline__ void mma16816h(float* c, const uint32_t* a, const uint32_t* b) {
    asm volatile(
        "mma.sync.aligned.m16n8k16.row.col.f32.f16.f16.f32 "
        "{%0,%1,%2,%3}, {%4,%5,%6,%7}, {%8,%9}, {%0,%1,%2,%3};"
        : "+f"(c[0]), "+f"(c[1]), "+f"(c[2]), "+f"(c[3])
        : "r"(a[0]), "r"(a[1]), "r"(a[2]), "r"(a[3]), "r"(b[0]), "r"(b[1]));
}

// ---------------- SMEM layout (bytes) ----------------
#define SM_Z    0                    // 128*136*2 = 34816 (z fp16, single)
#define SM_T    34816                // 128*72*2 = 18432 (tT fp16, single)
#define SM_FYH  53248                // 64*136*2 = 17408 each
#define SM_FYL  70656
#define SM_FXH  88064
#define SM_FXL  105472
#define SM_TOTAL 122880

__global__ __launch_bounds__(512, 1)
void filt_mma(const float* __restrict__ x, const float* __restrict__ xh,
              const float* __restrict__ hvec, const float* __restrict__ Ww,
              const float* __restrict__ Wb,
              float* __restrict__ out, int gridn) {
    extern __shared__ char sm[];
    __shared__ float s_par[5];
    __shared__ float s_red[32];
    __shared__ float s_inv[2];

    int tid = threadIdx.x;
    int wid = tid >> 5, lane = tid & 31;
    int grp = lane >> 3, li = lane & 7;
    int qt = lane >> 2;
    int qr = (lane & 3) * 2;

    // ======== prologue: params via warp-shuffle reductions ========
    if (wid < 5) {
        float p = 0.f;
        for (int j = lane; j < H_DIM; j += 32)
            p += __ldg(Ww + wid * H_DIM + j) * __ldg(hvec + j);
#pragma unroll
        for (int o = 16; o; o >>= 1) p += __shfl_xor_sync(0xFFFFFFFFu, p, o);
        if (lane == 0) s_par[wid] = p + __ldg(Wb + wid);
    }
    __syncthreads();

    float gX, gY, dd, i2v, gamma;
    {
        float var = expf(s_par[2] + 1e-8f);
        dd = expf(s_par[3]) * (float)(A_DIM - 1) / (float)(N_DIM - 1);
        gamma = expf(s_par[4]);
        gX = (float)(A_DIM + 1) * (s_par[0] + 1.f) * 0.5f;
        gY = (float)(A_DIM + 1) * (s_par[1] + 1.f) * 0.5f;
        i2v = 1.f / (2.f * var);
    }

    // pass 1: global sums
    {
        float sx = 0.f, sy = 0.f;
        for (int idx = tid; idx < N_DIM * A_DIM; idx += 512) {
            int n = idx >> 7, a = idx & 127;
            float off = ((float)n - (float)N_DIM * 0.5f - 0.5f) * dd;
            float da = (float)a - (gX + off);
            float db = (float)a - (gY + off);
            sx += expf(-da * da * i2v);
            sy += expf(-db * db * i2v);
        }
#pragma unroll
        for (int o = 16; o; o >>= 1) {
            sx += __shfl_xor_sync(0xFFFFFFFFu, sx, o);
            sy += __shfl_xor_sync(0xFFFFFFFFu, sy, o);
        }
        if (lane == 0) { s_red[wid] = sx; s_red[16 + wid] = sy; }
        __syncthreads();
        if (wid == 0) {
            float vx = (lane < 16) ? s_red[lane] : 0.f;
            float vy = (lane < 16) ? s_red[16 + lane] : 0.f;
#pragma unroll
            for (int o = 16; o; o >>= 1) {
                vx += __shfl_xor_sync(0xFFFFFFFFu, vx, o);
                vy += __shfl_xor_sync(0xFFFFFFFFu, vy, o);
            }
            if (lane == 0) { s_inv[0] = 1.f / vx; s_inv[1] = gamma / vy; }
        }
        __syncthreads();
    }
    float invX = s_inv[0], invYg = s_inv[1];

    // pass 2: fp16 hi/lo filterbank panels
    for (int idx = tid; idx < N_DIM * A_DIM; idx += 512) {
        int n = idx >> 7, a = idx & 127;
        float off = ((float)n - (float)N_DIM * 0.5f - 0.5f) * dd;
        float da = (float)a - (gX + off);
        float db = (float)a - (gY + off);
        float fy = expf(-db * db * i2v) * invYg;
        float fx = expf(-da * da * i2v) * invX;

        __half yh = __float2half_rn(fy);
        __half yl = __float2half_rn(fy - __half2float(yh));
        __half xhh = __float2half_rn(fx);
        __half xll = __float2half_rn(fx - __half2float(xhh));

        uint32_t o = (uint32_t)((n * FSTR + a) * 2);
        *(__half*)(sm + SM_FYH + o) = yh;
        *(__half*)(sm + SM_FYL + o) = yl;
        *(__half*)(sm + SM_FXH + o) = xhh;
        *(__half*)(sm + SM_FXL + o) = xll;
    }

    uint32_t sb = smem_u32(sm);
    int radd = (grp >> 1) * 8;
    int cadd = (grp & 1) * 8;

    bool is_compute = (wid < 8);
    int ltid = tid - 256;

    // loader: z(job) f32 -> fp16 panel (256 threads)
    auto ldz = [&](int job) {
        const float* src = ((job >> 10) ? xh : x) + (size_t)(job & 1023) * (A_DIM * A_DIM);
        const float4* s4 = (const float4*)src;
#pragma unroll
        for (int i = 0; i < 16; i++) {
            int e4 = ltid + (i << 8);
            float4 v = __ldg(s4 + e4);
            int e = e4 << 2;
            int a = e >> 7, b = e & 127;
            uint32_t hA = pkhf(v.x, v.y), hB = pkhf(v.z, v.w);
            *(uint2*)(sm + SM_Z + (uint32_t)((a * ZSTR + b) * 2)) = make_uint2(hA, hB);
        }
    };

    // ---- compute-warp mappings (wid < 8) ----
    // stage 1: 8 warps = 4 b-groups (32 wide) x 2 n-halves (32 wide)
    int bg2 = wid & 3, nhh = wid >> 2;
    int b0 = bg2 * 32;
    uint32_t offA1p0 = (uint32_t)(((li + radd) * ZSTR + b0 + cadd) * 2);
    uint32_t offA1p1 = offA1p0 + 32;
    uint32_t offB1[2];
#pragma unroll
    for (int q = 0; q < 2; q++)
        offB1[q] = (uint32_t)(((nhh * 32 + 16 * q + li + radd) * FSTR + cadd) * 2);

    // stage 2: 8 warps = 4 n-strips (16) x 2 m-halves (32)
    int n0 = (wid >> 1) * 16;
    int m0 = (wid & 1) * 32;
    uint32_t offA2 = (uint32_t)(((li + radd) * TSTR2 + n0 + cadd) * 2);
    uint32_t offB2[2];
#pragma unroll
    for (int q = 0; q < 2; q++)
        offB2[q] = (uint32_t)(((m0 + 16 * q + li + radd) * FSTR + cadd) * 2);

    if (!is_compute) ldz(blockIdx.x);
    __syncthreads();  // panels + z(0) visible

    for (int job = blockIdx.x; job < NJOBS; job += gridn) {
        int which = job >> 10;
        int img = job & 1023;

        // ---- stage 1: tT[b][n] = sum_a z[a][b]*Fy[n][a]  (zh*(fh+fl)) ----
        if (is_compute) {
            float acc[2][4][4];
#pragma unroll
            for (int p = 0; p < 2; p++)
#pragma unroll
                for (int j = 0; j < 4; j++)
#pragma unroll
                    for (int c = 0; c < 4; c++) acc[p][j][c] = 0.f;

#pragma unroll
            for (int s = 0; s < 8; s++) {
                uint32_t Ah[2][4], Bh[8], Bl[8];
                uint32_t abase = (uint32_t)(s * 16 * ZSTR * 2);
                ldsm4t(sb + SM_Z + offA1p0 + abase, Ah[0]);
                ldsm4t(sb + SM_Z + offA1p1 + abase, Ah[1]);
#pragma unroll
                for (int q = 0; q < 2; q++) {
                    uint32_t boff = offB1[q] + (uint32_t)(s * 32);
                    ldsm4(sb + SM_FYH + boff, Bh + 4 * q);
                    ldsm4(sb + SM_FYL + boff, Bl + 4 * q);
                }
#pragma unroll
                for (int p = 0; p < 2; p++)
#pragma unroll
                    for (int j = 0; j < 4; j++) mma16816h(acc[p][j], Ah[p], Bh + 2 * j);
#pragma unroll
                for (int p = 0; p < 2; p++)
#pragma unroll
                    for (int j = 0; j < 4; j++) mma16816h(acc[p][j], Ah[p], Bl + 2 * j);
            }

            // write tT (fp16, single panel)
#pragma unroll
            for (int p = 0; p < 2; p++) {
                int r0 = b0 + 16 * p + qt, r1 = r0 + 8;
#pragma unroll
                for (int j = 0; j < 4; j++) {
                    int nj2 = nhh * 32 + 8 * j + qr;
                    *(uint32_t*)(sm + SM_T + (r0 * TSTR2 + nj2) * 2) =
                        pkhf(acc[p][j][0], acc[p][j][1]);
                    *(uint32_t*)(sm + SM_T + (r1 * TSTR2 + nj2) * 2) =
                        pkhf(acc[p][j][2], acc[p][j][3]);
                }
            }
        }
        __syncthreads();  // tT ready; z buffer free

        if (!is_compute) {
            if (job + gridn < NJOBS) ldz(job + gridn);
        } else {
            // ---- stage 2: C[n][m] = sum_b t[n][b]*Fx[m][b]  (th*(fh+fl)) ----
            float acc[4][4];
#pragma unroll
            for (int j = 0; j < 4; j++)
#pragma unroll
                for (int c = 0; c < 4; c++) acc[j][c] = 0.f;

#pragma unroll
            for (int s = 0; s < 8; s++) {
                uint32_t Ah[4], Bh[8], Bl[8];
                uint32_t aoff = offA2 + (uint32_t)(s * 16 * TSTR2 * 2);
                ldsm4t(sb + SM_T + aoff, Ah);
#pragma unroll
                for (int q = 0; q < 2; q++) {
                    uint32_t boff = offB2[q] + (uint32_t)(s * 32);
                    ldsm4(sb + SM_FXH + boff, Bh + 4 * q);
                    ldsm4(sb + SM_FXL + boff, Bl + 4 * q);
                }
#pragma unroll
                for (int j = 0; j < 4; j++) mma16816h(acc[j], Ah, Bh + 2 * j);
#pragma unroll
                for (int j = 0; j < 4; j++) mma16816h(acc[j], Ah, Bl + 2 * j);
            }

            float* ob = out + (size_t)img * (2 * N_DIM * N_DIM) + which * (N_DIM * N_DIM);
            int nA = n0 + qt, nB = nA + 8;
#pragma unroll
            for (int j = 0; j < 4; j++) {
                int m = m0 + 8 * j + qr;
                *(float2*)(ob + nA * N_DIM + m) = make_float2(acc[j][0], acc[j][1]);
                *(float2*)(ob + nB * N_DIM + m) = make_float2(acc[j][2], acc[j][3]);
            }
        }
        __syncthreads();  // next z visible; tT free
    }
}

extern "C" void kernel_launch(void* const* d_in, const int* in_sizes, int n_in,
                              void* d_out, int out_size) {
    const float* x  = (const float*)d_in[0];
    const float* xh = (const float*)d_in[1];
    const float* h  = (const float*)d_in[2];
    const float* Ww = (const float*)d_in[3];
    const float* Wb = (const float*)d_in[4];
    float* out = (float*)d_out;

    int sms = 148;
    cudaDeviceGetAttribute(&sms, cudaDevAttrMultiProcessorCount, 0);
    if (sms <= 0) sms = 148;

    cudaFuncSetAttribute(filt_mma, cudaFuncAttributeMaxDynamicSharedMemorySize, SM_TOTAL);

    filt_mma<<<sms, 512, SM_TOTAL>>>(x, xh, h, Ww, Wb, out, sms);
}

// round 14
// speedup vs baseline: 1.8714x; 1.0425x over previous
#include <cuda_runtime.h>
#include <cuda_fp16.h>
#include <stdint.h>

#define A_DIM 128
#define N_DIM 64
#define H_DIM 1024
#define NJOBS 2048

#define ZSTR 136   // fp16 elems per z row
#define FSTR 136   // filterbank row stride
#define TSTR2 72   // tT row stride

// ---------------- helpers ----------------
__device__ __forceinline__ uint32_t smem_u32(const void* p) {
    uint32_t a;
    asm("{ .reg .u64 t; cvta.to.shared.u64 t, %1; cvt.u32.u64 %0, t; }" : "=r"(a) : "l"(p));
    return a;
}
__device__ __forceinline__ uint32_t pkhf(float lo, float hi) {
    uint32_t r;
    asm("cvt.rn.f16x2.f32 %0, %1, %2;" : "=r"(r) : "f"(hi), "f"(lo));
    return r;
}
__device__ __forceinline__ void ldsm4(uint32_t a, uint32_t* r) {
    asm volatile("ldmatrix.sync.aligned.m8n8.x4.shared.b16 {%0,%1,%2,%3}, [%4];"
                 : "=r"(r[0]), "=r"(r[1]), "=r"(r[2]), "=r"(r[3]) : "r"(a));
}
__device__ __forceinline__ void ldsm4t(uint32_t a, uint32_t* r) {
    asm volatile("ldmatrix.sync.aligned.m8n8.x4.trans.shared.b16 {%0,%1,%2,%3}, [%4];"
                 : "=r"(r[0]), "=r"(r[1]), "=r"(r[2]), "=r"(r[3]) : "r"(a));
}
__device__ __forceinline__ void mma16816h(float* c, const uint32_t* a, const uint32_t* b) {
    asm volatile(
        "mma.sync.aligned.m16n8k16.row.col.f32.f16.f16.f32 "
        "{%0,%1,%2,%3}, {%4,%5,%6,%7}, {%8,%9}, {%0,%1,%2,%3};"
        : "+f"(c[0]), "+f"(c[1]), "+f"(c[2]), "+f"(c[3])
        : "r"(a[0]), "r"(a[1]), "r"(a[2]), "r"(a[3]), "r"(b[0]), "r"(b[1]));
}

// ---------------- SMEM layout (bytes) ----------------
#define SM_Z0   0          // 34816 each (z fp16)
#define SM_Z1   34816
#define SM_T0   69632      // 18432 each (tT fp16)
#define SM_T1   88064
#define SM_FYH  106496     // 17408 each
#define SM_FYL  123904
#define SM_FXH  141312
#define SM_FXL  158720
#define SM_TOTAL 176128

__global__ __launch_bounds__(512, 1)
void filt_mma(const float* __restrict__ x, const float* __restrict__ xh,
              const float* __restrict__ hvec, const float* __restrict__ Ww,
              const float* __restrict__ Wb,
              float* __restrict__ out, int gridn) {
    extern __shared__ char sm[];
    __shared__ float s_par[5];
    __shared__ float s_red[32];
    __shared__ float s_inv[2];

    int tid = threadIdx.x;
    int wid = tid >> 5, lane = tid & 31;
    int grp = lane >> 3, li = lane & 7;
    int qt = lane >> 2;
    int qr = (lane & 3) * 2;

    // ======== prologue: params via warp-shuffle reductions ========
    if (wid < 5) {
        float p = 0.f;
        for (int j = lane; j < H_DIM; j += 32)
            p += __ldg(Ww + wid * H_DIM + j) * __ldg(hvec + j);
#pragma unroll
        for (int o = 16; o; o >>= 1) p += __shfl_xor_sync(0xFFFFFFFFu, p, o);
        if (lane == 0) s_par[wid] = p + __ldg(Wb + wid);
    }
    __syncthreads();

    float gX, gY, dd, i2v, gamma;
    {
        float var = expf(s_par[2] + 1e-8f);
        dd = expf(s_par[3]) * (float)(A_DIM - 1) / (float)(N_DIM - 1);
        gamma = expf(s_par[4]);
        gX = (float)(A_DIM + 1) * (s_par[0] + 1.f) * 0.5f;
        gY = (float)(A_DIM + 1) * (s_par[1] + 1.f) * 0.5f;
        i2v = 1.f / (2.f * var);
    }

    // pass 1: global sums
    {
        float sx = 0.f, sy = 0.f;
        for (int idx = tid; idx < N_DIM * A_DIM; idx += 512) {
            int n = idx >> 7, a = idx & 127;
            float off = ((float)n - (float)N_DIM * 0.5f - 0.5f) * dd;
            float da = (float)a - (gX + off);
            float db = (float)a - (gY + off);
            sx += expf(-da * da * i2v);
            sy += expf(-db * db * i2v);
        }
#pragma unroll
        for (int o = 16; o; o >>= 1) {
            sx += __shfl_xor_sync(0xFFFFFFFFu, sx, o);
            sy += __shfl_xor_sync(0xFFFFFFFFu, sy, o);
        }
        if (lane == 0) { s_red[wid] = sx; s_red[16 + wid] = sy; }
        __syncthreads();
        if (wid == 0) {
            float vx = (lane < 16) ? s_red[lane] : 0.f;
            float vy = (lane < 16) ? s_red[16 + lane] : 0.f;
#pragma unroll
            for (int o = 16; o; o >>= 1) {
                vx += __shfl_xor_sync(0xFFFFFFFFu, vx, o);
                vy += __shfl_xor_sync(0xFFFFFFFFu, vy, o);
            }
            if (lane == 0) { s_inv[0] = 1.f / vx; s_inv[1] = gamma / vy; }
        }
        __syncthreads();
    }
    float invX = s_inv[0], invYg = s_inv[1];

    // pass 2: fp16 hi/lo filterbank panels
    for (int idx = tid; idx < N_DIM * A_DIM; idx += 512) {
        int n = idx >> 7, a = idx & 127;
        float off = ((float)n - (float)N_DIM * 0.5f - 0.5f) * dd;
        float da = (float)a - (gX + off);
        float db = (float)a - (gY + off);
        float fy = expf(-db * db * i2v) * invYg;
        float fx = expf(-da * da * i2v) * invX;

        __half yh = __float2half_rn(fy);
        __half yl = __float2half_rn(fy - __half2float(yh));
        __half xhh = __float2half_rn(fx);
        __half xll = __float2half_rn(fx - __half2float(xhh));

        uint32_t o = (uint32_t)((n * FSTR + a) * 2);
        *(__half*)(sm + SM_FYH + o) = yh;
        *(__half*)(sm + SM_FYL + o) = yl;
        *(__half*)(sm + SM_FXH + o) = xhh;
        *(__half*)(sm + SM_FXL + o) = xll;
    }

    uint32_t sb = smem_u32(sm);
    int radd = (grp >> 1) * 8;
    int cadd = (grp & 1) * 8;

    // roles: wid 0-3 stage1, wid 4-7 stage2, wid 8-15 loader
    int role = (wid < 4) ? 0 : (wid < 8 ? 1 : 2);
    int ltid = tid - 256;

    // loader: z(job) f32 -> fp16 panel at zbase
    auto ldz = [&](int job, uint32_t zbase) {
        const float* src = ((job >> 10) ? xh : x) + (size_t)(job & 1023) * (A_DIM * A_DIM);
        const float4* s4 = (const float4*)src;
#pragma unroll
        for (int i = 0; i < 16; i++) {
            int e4 = ltid + (i << 8);
            float4 v = __ldg(s4 + e4);
            int e = e4 << 2;
            int a = e >> 7, b = e & 127;
            uint32_t hA = pkhf(v.x, v.y), hB = pkhf(v.z, v.w);
            *(uint2*)(sm + zbase + (uint32_t)((a * ZSTR + b) * 2)) = make_uint2(hA, hB);
        }
    };

    // ---- stage 1 mapping (wid 0-3): warp = 32 b-cols x full 64 n ----
    int b0 = (wid & 3) * 32;
    uint32_t offA1 = (uint32_t)(((li + radd) * ZSTR + b0 + cadd) * 2);
    uint32_t offB1[4];
#pragma unroll
    for (int q = 0; q < 4; q++)
        offB1[q] = (uint32_t)(((16 * q + li + radd) * FSTR + cadd) * 2);

    // ---- stage 2 mapping (wid 4-7): warp = 16 n-rows x full 64 m ----
    int n0 = (wid & 3) * 16;
    uint32_t offA2 = (uint32_t)(((li + radd) * TSTR2 + n0 + cadd) * 2);
    uint32_t offB2[4];
#pragma unroll
    for (int q = 0; q < 4; q++)
        offB2[q] = (uint32_t)(((16 * q + li + radd) * FSTR + cadd) * 2);

    int bx = blockIdx.x;
    int cnt = (NJOBS - bx + gridn - 1) / gridn;

    // prime z[0] with job 0
    if (role == 2) ldz(bx, SM_Z0);
    __syncthreads();  // panels + z(0) visible

    for (int it = 0; it <= cnt; it++) {
        uint32_t zbase = (it & 1) ? SM_Z1 : SM_Z0;
        uint32_t tbase = (it & 1) ? SM_T1 : SM_T0;
        uint32_t tprev = (it & 1) ? SM_T0 : SM_T1;

        if (role == 0 && it < cnt) {
            // ---- stage 1, job(it): tT[b][n] = sum_a z[a][b]*Fy[n][a] ----
            float acc[2][8][4];
#pragma unroll
            for (int p = 0; p < 2; p++)
#pragma unroll
                for (int j = 0; j < 8; j++)
#pragma unroll
                    for (int c = 0; c < 4; c++) acc[p][j][c] = 0.f;

#pragma unroll
            for (int s = 0; s < 8; s++) {
                uint32_t Af[2][4], B[16];
                uint32_t abase = (uint32_t)(s * 16 * ZSTR * 2);
                ldsm4t(sb + zbase + offA1 + abase, Af[0]);
                ldsm4t(sb + zbase + offA1 + abase + 32, Af[1]);  // b0+16 (16 cols * 2B)
#pragma unroll
                for (int q = 0; q < 4; q++)
                    ldsm4(sb + SM_FYH + offB1[q] + (uint32_t)(s * 32), B + 4 * q);
#pragma unroll
                for (int p = 0; p < 2; p++)
#pragma unroll
                    for (int j = 0; j < 8; j++) mma16816h(acc[p][j], Af[p], B + 2 * j);
#pragma unroll
                for (int q = 0; q < 4; q++)
                    ldsm4(sb + SM_FYL + offB1[q] + (uint32_t)(s * 32), B + 4 * q);
#pragma unroll
                for (int p = 0; p < 2; p++)
#pragma unroll
                    for (int j = 0; j < 8; j++) mma16816h(acc[p][j], Af[p], B + 2 * j);
            }

            // write tT (fp16)
#pragma unroll
            for (int p = 0; p < 2; p++) {
                int r0 = b0 + 16 * p + qt, r1 = r0 + 8;
#pragma unroll
                for (int j = 0; j < 8; j++) {
                    int nj2 = 8 * j + qr;
                    *(uint32_t*)(sm + tbase + (r0 * TSTR2 + nj2) * 2) =
                        pkhf(acc[p][j][0], acc[p][j][1]);
                    *(uint32_t*)(sm + tbase + (r1 * TSTR2 + nj2) * 2) =
                        pkhf(acc[p][j][2], acc[p][j][3]);
                }
            }
        } else if (role == 1 && it >= 1) {
            // ---- stage 2, job(it-1): C[n][m] = sum_b t[n][b]*Fx[m][b] ----
            int job = bx + (it - 1) * gridn;
            int which = job >> 10;
            int img = job & 1023;

            float acc[8][4];
#pragma unroll
            for (int j = 0; j < 8; j++)
#pragma unroll
                for (int c = 0; c < 4; c++) acc[j][c] = 0.f;

#pragma unroll
            for (int s = 0; s < 8; s++) {
                uint32_t Af[4], B[16];
                ldsm4t(sb + tprev + offA2 + (uint32_t)(s * 16 * TSTR2 * 2), Af);
#pragma unroll
                for (int q = 0; q < 4; q++)
                    ldsm4(sb + SM_FXH + offB2[q] + (uint32_t)(s * 32), B + 4 * q);
#pragma unroll
                for (int j = 0; j < 8; j++) mma16816h(acc[j], Af, B + 2 * j);
#pragma unroll
                for (int q = 0; q < 4; q++)
                    ldsm4(sb + SM_FXL + offB2[q] + (uint32_t)(s * 32), B + 4 * q);
#pragma unroll
                for (int j = 0; j < 8; j++) mma16816h(acc[j], Af, B + 2 * j);
            }

            float* ob = out + (size_t)img * (2 * N_DIM * N_DIM) + which * (N_DIM * N_DIM);
            int nA = n0 + qt, nB = nA + 8;
#pragma unroll
            for (int j = 0; j < 8; j++) {
                int m = 8 * j + qr;
                *(float2*)(ob + nA * N_DIM + m) = make_float2(acc[j][0], acc[j][1]);
                *(float2*)(ob + nB * N_DIM + m) = make_float2(acc[j][2], acc[j][3]);
            }
        } else if (role == 2 && it + 1 < cnt) {
            // ---- loader: z for job(it+1) into the other z buffer ----
            ldz(bx + (it + 1) * gridn, (it & 1) ? SM_Z0 : SM_Z1);
        }

        __syncthreads();  // seal: tT(it) for stage2, z(it+1) for stage1
    }
}

extern "C" void kernel_launch(void* const* d_in, const int* in_sizes, int n_in,
                              void* d_out, int out_size) {
    const float* x  = (const float*)d_in[0];
    const float* xh = (const float*)d_in[1];
    const float* h  = (const float*)d_in[2];
    const float* Ww = (const float*)d_in[3];
    const float* Wb = (const float*)d_in[4];
    float* out = (float*)d_out;

    int sms = 148;
    cudaDeviceGetAttribute(&sms, cudaDevAttrMultiProcessorCount, 0);
    if (sms <= 0) sms = 148;

    cudaFuncSetAttribute(filt_mma, cudaFuncAttributeMaxDynamicSharedMemorySize, SM_TOTAL);

    filt_mma<<<sms, 512, SM_TOTAL>>>(x, xh, h, Ww, Wb, out, sms);
}

// round 15
// speedup vs baseline: 2.2593x; 1.2073x over previous
#include <cuda_runtime.h>
#include <cuda_fp16.h>
#include <stdint.h>

#define A_DIM 128
#define N_DIM 64
#define H_DIM 1024
#define NJOBS 2048

#define ZSTR 136   // fp16 elems per z row
#define FSTR 136   // filterbank row stride
#define TSTR2 72   // tT row stride

// ---------------- helpers ----------------
__device__ __forceinline__ uint32_t smem_u32(const void* p) {
    uint32_t a;
    asm("{ .reg .u64 t; cvta.to.shared.u64 t, %1; cvt.u32.u64 %0, t; }" : "=r"(a) : "l"(p));
    return a;
}
__device__ __forceinline__ uint32_t pkhf(float lo, float hi) {
    uint32_t r;
    asm("cvt.rn.f16x2.f32 %0, %1, %2;" : "=r"(r) : "f"(hi), "f"(lo));
    return r;
}
__device__ __forceinline__ void ldsm4(uint32_t a, uint32_t* r) {
    asm volatile("ldmatrix.sync.aligned.m8n8.x4.shared.b16 {%0,%1,%2,%3}, [%4];"
                 : "=r"(r[0]), "=r"(r[1]), "=r"(r[2]), "=r"(r[3]) : "r"(a));
}
__device__ __forceinline__ void ldsm4t(uint32_t a, uint32_t* r) {
    asm volatile("ldmatrix.sync.aligned.m8n8.x4.trans.shared.b16 {%0,%1,%2,%3}, [%4];"
                 : "=r"(r[0]), "=r"(r[1]), "=r"(r[2]), "=r"(r[3]) : "r"(a));
}
__device__ __forceinline__ void mma16816h(float* c, const uint32_t* a, const uint32_t* b) {
    asm volatile(
        "mma.sync.aligned.m16n8k16.row.col.f32.f16.f16.f32 "
        "{%0,%1,%2,%3}, {%4,%5,%6,%7}, {%8,%9}, {%0,%1,%2,%3};"
        : "+f"(c[0]), "+f"(c[1]), "+f"(c[2]), "+f"(c[3])
        : "r"(a[0]), "r"(a[1]), "r"(a[2]), "r"(a[3]), "r"(b[0]), "r"(b[1]));
}

// ---------------- SMEM layout (bytes) ----------------
#define SM_Z0   0          // 34816 each (z fp16)
#define SM_Z1   34816
#define SM_T0   69632      // 18432 each (tT fp16)
#define SM_T1   88064
#define SM_FY   106496     // 17408 each (fp16, single panel)
#define SM_FX   123904
#define SM_TOTAL 141312

__global__ __launch_bounds__(512, 1)
void filt_mma(const float* __restrict__ x, const float* __restrict__ xh,
              const float* __restrict__ hvec, const float* __restrict__ Ww,
              const float* __restrict__ Wb,
              float* __restrict__ out, int gridn) {
    extern __shared__ char sm[];
    __shared__ float s_par[5];
    __shared__ float s_red[32];
    __shared__ float s_inv[2];

    int tid = threadIdx.x;
    int wid = tid >> 5, lane = tid & 31;
    int grp = lane >> 3, li = lane & 7;
    int qt = lane >> 2;
    int qr = (lane & 3) * 2;

    // ======== prologue: params via warp-shuffle reductions ========
    if (wid < 5) {
        float p = 0.f;
        for (int j = lane; j < H_DIM; j += 32)
            p += __ldg(Ww + wid * H_DIM + j) * __ldg(hvec + j);
#pragma unroll
        for (int o = 16; o; o >>= 1) p += __shfl_xor_sync(0xFFFFFFFFu, p, o);
        if (lane == 0) s_par[wid] = p + __ldg(Wb + wid);
    }
    __syncthreads();

    float gX, gY, dd, i2v, gamma;
    {
        float var = expf(s_par[2] + 1e-8f);
        dd = expf(s_par[3]) * (float)(A_DIM - 1) / (float)(N_DIM - 1);
        gamma = expf(s_par[4]);
        gX = (float)(A_DIM + 1) * (s_par[0] + 1.f) * 0.5f;
        gY = (float)(A_DIM + 1) * (s_par[1] + 1.f) * 0.5f;
        i2v = 1.f / (2.f * var);
    }

    // pass 1: global sums
    {
        float sx = 0.f, sy = 0.f;
        for (int idx = tid; idx < N_DIM * A_DIM; idx += 512) {
            int n = idx >> 7, a = idx & 127;
            float off = ((float)n - (float)N_DIM * 0.5f - 0.5f) * dd;
            float da = (float)a - (gX + off);
            float db = (float)a - (gY + off);
            sx += expf(-da * da * i2v);
            sy += expf(-db * db * i2v);
        }
#pragma unroll
        for (int o = 16; o; o >>= 1) {
            sx += __shfl_xor_sync(0xFFFFFFFFu, sx, o);
            sy += __shfl_xor_sync(0xFFFFFFFFu, sy, o);
        }
        if (lane == 0) { s_red[wid] = sx; s_red[16 + wid] = sy; }
        __syncthreads();
        if (wid == 0) {
            float vx = (lane < 16) ? s_red[lane] : 0.f;
            float vy = (lane < 16) ? s_red[16 + lane] : 0.f;
#pragma unroll
            for (int o = 16; o; o >>= 1) {
                vx += __shfl_xor_sync(0xFFFFFFFFu, vx, o);
                vy += __shfl_xor_sync(0xFFFFFFFFu, vy, o);
            }
            if (lane == 0) { s_inv[0] = 1.f / vx; s_inv[1] = gamma / vy; }
        }
        __syncthreads();
    }
    float invX = s_inv[0], invYg = s_inv[1];

    // pass 2: fp16 filterbank panels (single precision term)
    for (int idx = tid; idx < N_DIM * A_DIM; idx += 512) {
        int n = idx >> 7, a = idx & 127;
        float off = ((float)n - (float)N_DIM * 0.5f - 0.5f) * dd;
        float da = (float)a - (gX + off);
        float db = (float)a - (gY + off);
        float fy = expf(-db * db * i2v) * invYg;
        float fx = expf(-da * da * i2v) * invX;

        uint32_t o = (uint32_t)((n * FSTR + a) * 2);
        *(__half*)(sm + SM_FY + o) = __float2half_rn(fy);
        *(__half*)(sm + SM_FX + o) = __float2half_rn(fx);
    }

    uint32_t sb = smem_u32(sm);
    int radd = (grp >> 1) * 8;
    int cadd = (grp & 1) * 8;

    bool is_compute = (wid < 8);
    int ltid = tid - 256;

    // loader: z(job) f32 -> fp16 panel at zbase
    auto ldz = [&](int job, uint32_t zbase) {
        const float* src = ((job >> 10) ? xh : x) + (size_t)(job & 1023) * (A_DIM * A_DIM);
        const float4* s4 = (const float4*)src;
#pragma unroll
        for (int i = 0; i < 16; i++) {
            int e4 = ltid + (i << 8);
            float4 v = __ldg(s4 + e4);
            int e = e4 << 2;
            int a = e >> 7, b = e & 127;
            uint32_t hA = pkhf(v.x, v.y), hB = pkhf(v.z, v.w);
            *(uint2*)(sm + zbase + (uint32_t)((a * ZSTR + b) * 2)) = make_uint2(hA, hB);
        }
    };

    // ---- stage 1 mapping (compute warps): warp = 16 b-cols x full 64 n ----
    int b0 = wid * 16;     // wid 0..7 -> b 0..127
    uint32_t offA1 = (uint32_t)(((li + radd) * ZSTR + b0 + cadd) * 2);
    uint32_t offB1[4];
#pragma unroll
    for (int q = 0; q < 4; q++)
        offB1[q] = (uint32_t)(((16 * q + li + radd) * FSTR + cadd) * 2);

    // ---- stage 2 mapping (compute warps): warp = 16 n-rows x 32 m-cols ----
    int n0 = (wid >> 1) * 16;
    int m0 = (wid & 1) * 32;
    uint32_t offA2 = (uint32_t)(((li + radd) * TSTR2 + n0 + cadd) * 2);
    uint32_t offB2[2];
#pragma unroll
    for (int q = 0; q < 2; q++)
        offB2[q] = (uint32_t)(((m0 + 16 * q + li + radd) * FSTR + cadd) * 2);

    int bx = blockIdx.x;
    int cnt = (NJOBS - bx + gridn - 1) / gridn;

    // prime z[0] with job 0
    if (!is_compute) ldz(bx, SM_Z0);
    __syncthreads();  // panels + z(0) visible

    for (int it = 0; it <= cnt; it++) {
        uint32_t zbase = (it & 1) ? SM_Z1 : SM_Z0;
        uint32_t tbase = (it & 1) ? SM_T1 : SM_T0;
        uint32_t tprev = (it & 1) ? SM_T0 : SM_T1;

        if (is_compute) {
            // ---- stage 1, job(it): tT[b][n] = sum_a z[a][b]*Fy[n][a] ----
            if (it < cnt) {
                float acc[8][4];
#pragma unroll
                for (int j = 0; j < 8; j++)
#pragma unroll
                    for (int c = 0; c < 4; c++) acc[j][c] = 0.f;

#pragma unroll
                for (int s = 0; s < 8; s++) {
                    uint32_t Af[4], B[16];
                    ldsm4t(sb + zbase + offA1 + (uint32_t)(s * 16 * ZSTR * 2), Af);
#pragma unroll
                    for (int q = 0; q < 4; q++)
                        ldsm4(sb + SM_FY + offB1[q] + (uint32_t)(s * 32), B + 4 * q);
#pragma unroll
                    for (int j = 0; j < 8; j++) mma16816h(acc[j], Af, B + 2 * j);
                }

                // write tT (fp16)
                int r0 = b0 + qt, r1 = r0 + 8;
#pragma unroll
                for (int j = 0; j < 8; j++) {
                    int nj2 = 8 * j + qr;
                    *(uint32_t*)(sm + tbase + (r0 * TSTR2 + nj2) * 2) =
                        pkhf(acc[j][0], acc[j][1]);
                    *(uint32_t*)(sm + tbase + (r1 * TSTR2 + nj2) * 2) =
                        pkhf(acc[j][2], acc[j][3]);
                }
            }

            // ---- stage 2, job(it-1): C[n][m] = sum_b t[n][b]*Fx[m][b] ----
            if (it >= 1) {
                int job = bx + (it - 1) * gridn;
                int which = job >> 10;
                int img = job & 1023;

                float acc[4][4];
#pragma unroll
                for (int j = 0; j < 4; j++)
#pragma unroll
                    for (int c = 0; c < 4; c++) acc[j][c] = 0.f;

#pragma unroll
                for (int s = 0; s < 8; s++) {
                    uint32_t Af[4], B[8];
                    ldsm4t(sb + tprev + offA2 + (uint32_t)(s * 16 * TSTR2 * 2), Af);
#pragma unroll
                    for (int q = 0; q < 2; q++)
                        ldsm4(sb + SM_FX + offB2[q] + (uint32_t)(s * 32), B + 4 * q);
#pragma unroll
                    for (int j = 0; j < 4; j++) mma16816h(acc[j], Af, B + 2 * j);
                }

                float* ob = out + (size_t)img * (2 * N_DIM * N_DIM) + which * (N_DIM * N_DIM);
                int nA = n0 + qt, nB = nA + 8;
#pragma unroll
                for (int j = 0; j < 4; j++) {
                    int m = m0 + 8 * j + qr;
                    *(float2*)(ob + nA * N_DIM + m) = make_float2(acc[j][0], acc[j][1]);
                    *(float2*)(ob + nB * N_DIM + m) = make_float2(acc[j][2], acc[j][3]);
                }
            }
        } else if (it + 1 < cnt) {
            // ---- loader: z for job(it+1) into the other z buffer ----
            ldz(bx + (it + 1) * gridn, (it & 1) ? SM_Z0 : SM_Z1);
        }

        __syncthreads();  // seal: tT(it) for next stage2, z(it+1) for next stage1
    }
}

extern "C" void kernel_launch(void* const* d_in, const int* in_sizes, int n_in,
                              void* d_out, int out_size) {
    const float* x  = (const float*)d_in[0];
    const float* xh = (const float*)d_in[1];
    const float* h  = (const float*)d_in[2];
    const float* Ww = (const float*)d_in[3];
    const float* Wb = (const float*)d_in[4];
    float* out = (float*)d_out;

    int sms = 148;
    cudaDeviceGetAttribute(&sms, cudaDevAttrMultiProcessorCount, 0);
    if (sms <= 0) sms = 148;

    cudaFuncSetAttribute(filt_mma, cudaFuncAttributeMaxDynamicSharedMemorySize, SM_TOTAL);

    filt_mma<<<sms, 512, SM_TOTAL>>>(x, xh, h, Ww, Wb, out, sms);
}